// round 2
// baseline (speedup 1.0000x reference)
#include <cuda_runtime.h>
#include <math.h>

// ---------------------------------------------------------------------------
// TemporalTransformer forward, fp32 baseline.
// x:[4,1024,1024], 4 layers of (preLN attn w/ bias-dots) + (preLN GELU FF),
// final LN. All GEMMs via a templated fp32 SGEMM (128x128x8 tiles, 8x8/thread,
// double-buffered smem) with fused epilogues.
// ---------------------------------------------------------------------------

#define DIMM   1024
#define DEPTH  4
#define HEADS  16
#define DHEAD  64
#define INNER  1024
#define FFI    4096
#define BB     4
#define TT     1024
#define MTOK   (BB*TT)     // 4096 tokens
#define NBH    (BB*HEADS)  // 64 batched heads

// -------------------- device-global scratch (no allocs allowed) ------------
__device__ float g_x   [MTOK*DIMM];        // residual stream         16 MB
__device__ float g_h   [MTOK*DIMM];        // LN output               16 MB
__device__ float g_qkv [MTOK*3*INNER];     // qkv projection          48 MB
__device__ float g_qkvb[MTOK*2*INNER];     // bias projection (q,k)   32 MB
__device__ float g_QQ  [NBH*TT*128];       // packed scale*[q|qb]     32 MB
__device__ float g_KKt [NBH*128*TT];       // packed [k|kb]^T         32 MB
__device__ float g_sc  [67108864];         // attention scores       256 MB
__device__ float g_ao  [MTOK*INNER];       // attn out (merged heads) 16 MB
__device__ float g_ff  [MTOK*FFI];         // FF hidden               64 MB

// -------------------- block reductions (256 threads fixed) -----------------
__device__ __forceinline__ float blk_sum(float v) {
    __shared__ float sh[32];
    int lane = threadIdx.x & 31, w = threadIdx.x >> 5;
    #pragma unroll
    for (int o = 16; o; o >>= 1) v += __shfl_xor_sync(0xffffffffu, v, o);
    if (lane == 0) sh[w] = v;
    __syncthreads();
    if (w == 0) {
        v = (lane < 8) ? sh[lane] : 0.0f;
        #pragma unroll
        for (int o = 4; o; o >>= 1) v += __shfl_xor_sync(0xffffffffu, v, o);
        if (lane == 0) sh[0] = v;
    }
    __syncthreads();
    v = sh[0];
    __syncthreads();
    return v;
}

__device__ __forceinline__ float blk_max(float v) {
    __shared__ float sh[32];
    int lane = threadIdx.x & 31, w = threadIdx.x >> 5;
    #pragma unroll
    for (int o = 16; o; o >>= 1) v = fmaxf(v, __shfl_xor_sync(0xffffffffu, v, o));
    if (lane == 0) sh[w] = v;
    __syncthreads();
    if (w == 0) {
        v = (lane < 8) ? sh[lane] : -INFINITY;
        #pragma unroll
        for (int o = 4; o; o >>= 1) v = fmaxf(v, __shfl_xor_sync(0xffffffffu, v, o));
        if (lane == 0) sh[0] = v;
    }
    __syncthreads();
    v = sh[0];
    __syncthreads();
    return v;
}

// -------------------- LayerNorm: one block per row (1024 wide) -------------
__global__ void ln_k(const float* __restrict__ x, const float* __restrict__ g,
                     const float* __restrict__ b, float* __restrict__ o) {
    long row = blockIdx.x;
    float4 v = ((const float4*)(x + row * DIMM))[threadIdx.x];
    float mu = blk_sum(v.x + v.y + v.z + v.w) * (1.0f / DIMM);
    float dx = v.x - mu, dy = v.y - mu, dz = v.z - mu, dw = v.w - mu;
    float var = blk_sum(dx * dx + dy * dy + dz * dz + dw * dw) * (1.0f / DIMM);
    float inv = rsqrtf(var + 1e-5f);
    float4 gg = ((const float4*)g)[threadIdx.x];
    float4 bb = ((const float4*)b)[threadIdx.x];
    float4 r;
    r.x = dx * inv * gg.x + bb.x;
    r.y = dy * inv * gg.y + bb.y;
    r.z = dz * inv * gg.z + bb.z;
    r.w = dw * inv * gg.w + bb.w;
    ((float4*)(o + row * DIMM))[threadIdx.x] = r;
}

// -------------------- softmax over last axis (rows of 1024) ----------------
__global__ void softmax_k(float* __restrict__ s) {
    float4* row = (float4*)(s + (long)blockIdx.x * TT);
    float4 v = row[threadIdx.x];
    float m = blk_max(fmaxf(fmaxf(v.x, v.y), fmaxf(v.z, v.w)));
    v.x = expf(v.x - m); v.y = expf(v.y - m);
    v.z = expf(v.z - m); v.w = expf(v.w - m);
    float inv = 1.0f / blk_sum(v.x + v.y + v.z + v.w);
    v.x *= inv; v.y *= inv; v.z *= inv; v.w *= inv;
    row[threadIdx.x] = v;
}

// -------------------- pack q|qb (scaled) and [k|kb]^T per head -------------
__global__ void pack_qk(const float* __restrict__ qkv, const float* __restrict__ qkvb,
                        float* __restrict__ QQ, float* __restrict__ KKt, float scale) {
    int idx = blockIdx.x * blockDim.x + threadIdx.x;   // NBH*TT*128 total
    int d  = idx & 127;
    int i  = (idx >> 7) & (TT - 1);
    int bh = idx >> 17;
    int b = bh >> 4, h = bh & 15;
    long tok = (long)b * TT + i;
    float q, k;
    if (d < 64) {
        q = qkv[tok * 3072 + h * 64 + d];
        k = qkv[tok * 3072 + INNER + h * 64 + d];
    } else {
        q = qkvb[tok * 2048 + h * 64 + (d - 64)];
        k = qkvb[tok * 2048 + INNER + h * 64 + (d - 64)];
    }
    QQ[idx] = q * scale;
    KKt[((long)bh * 128 + d) * TT + i] = k;
}

// -------------------- templated fp32 SGEMM ---------------------------------
// C[m,n] = sum_k A[m,k]*B[k,n]  (+ epilogue). All dims divisible by tiles.
// Batch offset per blockIdx.z: off = (z>>4)*s_b + (z&15)*s_h  (handles both
// linear batching and the (batch,head) split addressing of attention).
// EPI: 0 = plain, 1 = +bias[n]+resid[m,n], 2 = gelu(acc+bias[n])

__device__ __forceinline__ float gelu_f(float x) {
    return 0.5f * x * (1.0f + erff(x * 0.70710678118654752440f));
}

template<int BM, int BN, int BK, int TM, int TN, int EPI>
__global__ void __launch_bounds__(256) gemm_k(
    const float* __restrict__ Ag, const float* __restrict__ Bg, float* __restrict__ Cg,
    int lda, int ldb, int ldc, int K,
    long sAb, long sAh, long sBb, long sBh, long sCb, long sCh,
    const float* __restrict__ bias, const float* __restrict__ resid, int ldr)
{
    constexpr int TX = BN / TN, TY = BM / TM, NT = TX * TY;
    static_assert(NT == 256, "256 threads");
    __shared__ __align__(16) float As[2][BK][BM];
    __shared__ __align__(16) float Bs[2][BK][BN];

    const int z = blockIdx.z;
    const float* A = Ag + (long)(z >> 4) * sAb + (long)(z & 15) * sAh;
    const float* B = Bg + (long)(z >> 4) * sBb + (long)(z & 15) * sBh;
    float*       C = Cg + (long)(z >> 4) * sCb + (long)(z & 15) * sCh;

    const int bm = blockIdx.y * BM, bn = blockIdx.x * BN;
    const int tid = threadIdx.x;
    const int tx = tid % TX, ty = tid / TX;

    float acc[TM][TN];
    #pragma unroll
    for (int i = 0; i < TM; i++)
        #pragma unroll
        for (int j = 0; j < TN; j++) acc[i][j] = 0.0f;

    auto loadTile = [&](int k0, int buf) {
        constexpr int AV = BM * BK / 4;            // float4s in A tile
        #pragma unroll
        for (int v = 0; v < (AV + NT - 1) / NT; v++) {
            int t = v * NT + tid;
            if ((AV % NT == 0) || (t < AV)) {
                int r = t / (BK / 4);
                int c = (t % (BK / 4)) * 4;
                float4 f = *(const float4*)&A[(long)(bm + r) * lda + k0 + c];
                As[buf][c + 0][r] = f.x;
                As[buf][c + 1][r] = f.y;
                As[buf][c + 2][r] = f.z;
                As[buf][c + 3][r] = f.w;
            }
        }
        constexpr int BV = BK * BN / 4;            // float4s in B tile
        #pragma unroll
        for (int v = 0; v < (BV + NT - 1) / NT; v++) {
            int t = v * NT + tid;
            if ((BV % NT == 0) || (t < BV)) {
                int r = t / (BN / 4);
                int c = (t % (BN / 4)) * 4;
                *(float4*)&Bs[buf][r][c] =
                    *(const float4*)&B[(long)(k0 + r) * ldb + bn + c];
            }
        }
    };

    loadTile(0, 0);
    __syncthreads();
    int cur = 0;
    for (int kt = 0; kt < K; kt += BK) {
        if (kt + BK < K) loadTile(kt + BK, cur ^ 1);
        #pragma unroll
        for (int k = 0; k < BK; k++) {
            float a[TM], bf[TN];
            if constexpr (TM == 8) {
                float4 a0 = *(const float4*)&As[cur][k][ty * 4];
                float4 a1 = *(const float4*)&As[cur][k][BM / 2 + ty * 4];
                a[0]=a0.x; a[1]=a0.y; a[2]=a0.z; a[3]=a0.w;
                a[4]=a1.x; a[5]=a1.y; a[6]=a1.z; a[7]=a1.w;
            } else {
                float4 a0 = *(const float4*)&As[cur][k][ty * 4];
                a[0]=a0.x; a[1]=a0.y; a[2]=a0.z; a[3]=a0.w;
            }
            if constexpr (TN == 8) {
                float4 b0 = *(const float4*)&Bs[cur][k][tx * 4];
                float4 b1 = *(const float4*)&Bs[cur][k][BN / 2 + tx * 4];
                bf[0]=b0.x; bf[1]=b0.y; bf[2]=b0.z; bf[3]=b0.w;
                bf[4]=b1.x; bf[5]=b1.y; bf[6]=b1.z; bf[7]=b1.w;
            } else {
                float4 b0 = *(const float4*)&Bs[cur][k][tx * 4];
                bf[0]=b0.x; bf[1]=b0.y; bf[2]=b0.z; bf[3]=b0.w;
            }
            #pragma unroll
            for (int i = 0; i < TM; i++)
                #pragma unroll
                for (int j = 0; j < TN; j++)
                    acc[i][j] = fmaf(a[i], bf[j], acc[i][j]);
        }
        __syncthreads();
        cur ^= 1;
    }

    #pragma unroll
    for (int i = 0; i < TM; i++) {
        int m = bm + ((TM == 8) ? ((i < 4) ? ty * 4 + i : BM / 2 + ty * 4 + (i - 4))
                                : ty * 4 + i);
        #pragma unroll
        for (int j = 0; j < TN; j++) {
            int n = bn + ((TN == 8) ? ((j < 4) ? tx * 4 + j : BN / 2 + tx * 4 + (j - 4))
                                    : tx * 4 + j);
            float v = acc[i][j];
            if constexpr (EPI == 1) v = v + bias[n] + resid[(long)m * ldr + n];
            if constexpr (EPI == 2) v = gelu_f(v + bias[n]);
            C[(long)m * ldc + n] = v;
        }
    }
}

// -------------------- host orchestration -----------------------------------
extern "C" void kernel_launch(void* const* d_in, const int* in_sizes, int n_in,
                              void* d_out, int out_size) {
    (void)in_sizes; (void)n_in; (void)out_size;
    const float* x    = (const float*)d_in[0];
    const float* bias = (const float*)d_in[1];
    const float* wqkv = (const float*)d_in[2];
    const float* wout = (const float*)d_in[3];
    const float* bout = (const float*)d_in[4];
    const float* ln1g = (const float*)d_in[5];
    const float* ln1b = (const float*)d_in[6];
    const float* w1   = (const float*)d_in[7];
    const float* b1   = (const float*)d_in[8];
    const float* w2   = (const float*)d_in[9];
    const float* b2   = (const float*)d_in[10];
    const float* ln2g = (const float*)d_in[11];
    const float* ln2b = (const float*)d_in[12];
    const float* lnfg = (const float*)d_in[13];
    const float* lnfb = (const float*)d_in[14];

    // Resolve scratch addresses every call (no static guards — deterministic,
    // capture-safe driver queries, no stream operations involved).
    float *px, *ph, *pqkv, *pqkvb, *pQQ, *pKKt, *psc, *pao, *pff;
    cudaGetSymbolAddress((void**)&px,    g_x);
    cudaGetSymbolAddress((void**)&ph,    g_h);
    cudaGetSymbolAddress((void**)&pqkv,  g_qkv);
    cudaGetSymbolAddress((void**)&pqkvb, g_qkvb);
    cudaGetSymbolAddress((void**)&pQQ,   g_QQ);
    cudaGetSymbolAddress((void**)&pKKt,  g_KKt);
    cudaGetSymbolAddress((void**)&psc,   g_sc);
    cudaGetSymbolAddress((void**)&pao,   g_ao);
    cudaGetSymbolAddress((void**)&pff,   g_ff);

    cudaMemcpyAsync(px, x, sizeof(float) * MTOK * DIMM, cudaMemcpyDeviceToDevice);

    const float scale = 0.125f;  // DHEAD^-0.5

    for (int l = 0; l < DEPTH; l++) {
        const float* wqkv_l = wqkv + (long)l * DIMM * 3 * INNER;
        const float* wout_l = wout + (long)l * INNER * DIMM;
        const float* w1_l   = w1   + (long)l * DIMM * FFI;
        const float* w2_l   = w2   + (long)l * FFI * DIMM;

        // LN1
        ln_k<<<MTOK, 256>>>(px, ln1g + l * DIMM, ln1b + l * DIMM, ph);

        // qkv = ln(x) @ wqkv  [4096 x 3072]
        gemm_k<128,128,8,8,8,0><<<dim3(3 * INNER / 128, MTOK / 128, 1), 256>>>(
            ph, wqkv_l, pqkv, DIMM, 3 * INNER, 3 * INNER, DIMM,
            0, 0, 0, 0, 0, 0, nullptr, nullptr, 0);

        // qkvb = bias @ wqkv[:, :2048]  (only q,k parts used)
        gemm_k<128,128,8,8,8,0><<<dim3(2 * INNER / 128, MTOK / 128, 1), 256>>>(
            bias, wqkv_l, pqkvb, DIMM, 3 * INNER, 2 * INNER, DIMM,
            0, 0, 0, 0, 0, 0, nullptr, nullptr, 0);

        // pack scale*[q|qb] and [k|kb]^T  per (b,h)
        pack_qk<<<(NBH * TT * 128) / 256, 256>>>(pqkv, pqkvb, pQQ, pKKt, scale);

        // scores[bh] = QQ[bh] (1024x128) @ KKt[bh] (128x1024)
        gemm_k<128,128,8,8,8,0><<<dim3(TT / 128, TT / 128, NBH), 256>>>(
            pQQ, pKKt, psc, 128, TT, TT, 128,
            (long)16 * TT * 128, (long)TT * 128,
            (long)16 * 128 * TT, (long)128 * TT,
            (long)16 * TT * TT,  (long)TT * TT,
            nullptr, nullptr, 0);

        // softmax rows
        softmax_k<<<NBH * TT, 256>>>(psc);

        // attn_out[bh] = scores[bh] (1024x1024) @ V[bh] (1024x64), merged heads
        gemm_k<128,64,8,8,4,0><<<dim3(1, TT / 128, NBH), 256>>>(
            psc, pqkv + 2 * INNER, pao, TT, 3 * INNER, INNER, TT,
            (long)16 * TT * TT, (long)TT * TT,
            (long)TT * 3 * INNER, 64L,
            (long)TT * INNER, 64L,
            nullptr, nullptr, 0);

        // x = x + attn_out @ wout + bout
        gemm_k<128,128,8,8,8,1><<<dim3(DIMM / 128, MTOK / 128, 1), 256>>>(
            pao, wout_l, px, INNER, DIMM, DIMM, INNER,
            0, 0, 0, 0, 0, 0, bout + l * DIMM, px, DIMM);

        // LN2
        ln_k<<<MTOK, 256>>>(px, ln2g + l * DIMM, ln2b + l * DIMM, ph);

        // ff = gelu(ln(x) @ w1 + b1)
        gemm_k<128,128,8,8,8,2><<<dim3(FFI / 128, MTOK / 128, 1), 256>>>(
            ph, w1_l, pff, DIMM, FFI, FFI, DIMM,
            0, 0, 0, 0, 0, 0, b1 + l * FFI, nullptr, 0);

        // x = x + ff @ w2 + b2
        gemm_k<128,128,8,8,8,1><<<dim3(DIMM / 128, MTOK / 128, 1), 256>>>(
            pff, w2_l, px, FFI, DIMM, DIMM, FFI,
            0, 0, 0, 0, 0, 0, b2 + l * DIMM, px, DIMM);
    }

    // final LN -> output
    ln_k<<<MTOK, 256>>>(px, lnfg, lnfb, (float*)d_out);
}

// round 4
// speedup vs baseline: 2.3402x; 2.3402x over previous
#include <cuda_runtime.h>
#include <cuda_bf16.h>
#include <math.h>

// ---------------------------------------------------------------------------
// TemporalTransformer forward. GEMMs on tensor cores via bf16x3 split
// (hi/lo decomposition, 3x mma.sync.m16n8k16 per logical fp32 MMA).
// Producers emit bf16 hi/lo [row][k]; GEMM is cp.async + ldmatrix + mma.
// ---------------------------------------------------------------------------

#define DIMM   1024
#define DEPTH  4
#define HEADS  16
#define INNER  1024
#define FFI    4096
#define BB     4
#define TT     1024
#define MTOK   (BB*TT)
#define NBH    (BB*HEADS)

typedef __nv_bfloat16 bf16;
typedef __nv_bfloat162 bf162;

// -------------------- device-global scratch --------------------------------
__device__ float g_x   [MTOK*DIMM];
__device__ float g_qkv [MTOK*3*INNER];
__device__ float g_qkvb[MTOK*2*INNER];
__device__ float g_sc  [(long)NBH*TT*TT];

__device__ bf16 g_h_hi [MTOK*DIMM],      g_h_lo [MTOK*DIMM];
__device__ bf16 g_bias_hi[MTOK*DIMM],    g_bias_lo[MTOK*DIMM];
__device__ bf16 g_QQ_hi[NBH*TT*128],     g_QQ_lo[NBH*TT*128];
__device__ bf16 g_KK_hi[NBH*TT*128],     g_KK_lo[NBH*TT*128];
__device__ bf16 g_VT_hi[NBH*64*TT],      g_VT_lo[NBH*64*TT];
__device__ bf16 g_scb_hi[(long)NBH*TT*TT], g_scb_lo[(long)NBH*TT*TT];
__device__ bf16 g_ao_hi[MTOK*INNER],     g_ao_lo[MTOK*INNER];
__device__ bf16 g_ff_hi[(long)MTOK*FFI], g_ff_lo[(long)MTOK*FFI];
__device__ bf16 g_wqkvT_hi[DEPTH*3072*1024], g_wqkvT_lo[DEPTH*3072*1024];
__device__ bf16 g_woutT_hi[DEPTH*1024*1024], g_woutT_lo[DEPTH*1024*1024];
__device__ bf16 g_w1T_hi [DEPTH*4096*1024], g_w1T_lo [DEPTH*4096*1024];
__device__ bf16 g_w2T_hi [DEPTH*1024*4096], g_w2T_lo [DEPTH*1024*4096];

// -------------------- helpers ----------------------------------------------
__device__ __forceinline__ void bsplit(float v, bf16& h, bf16& l) {
    bf16 hb = __float2bfloat16_rz(v);          // truncate
    h = hb;
    l = __float2bfloat16(v - __bfloat162float(hb));
}

__device__ __forceinline__ float gelu_f(float x) {
    return 0.5f * x * (1.0f + erff(x * 0.70710678118654752440f));
}

__device__ __forceinline__ void ldm4(unsigned& r0, unsigned& r1, unsigned& r2,
                                     unsigned& r3, unsigned a) {
    asm volatile("ldmatrix.sync.aligned.m8n8.x4.shared.b16 {%0,%1,%2,%3}, [%4];"
                 : "=r"(r0), "=r"(r1), "=r"(r2), "=r"(r3) : "r"(a));
}

__device__ __forceinline__ void mma16816(float* d, const unsigned* a,
                                         unsigned b0, unsigned b1) {
    asm volatile(
        "mma.sync.aligned.m16n8k16.row.col.f32.bf16.bf16.f32 "
        "{%0,%1,%2,%3}, {%4,%5,%6,%7}, {%8,%9}, {%0,%1,%2,%3};"
        : "+f"(d[0]), "+f"(d[1]), "+f"(d[2]), "+f"(d[3])
        : "r"(a[0]), "r"(a[1]), "r"(a[2]), "r"(a[3]), "r"(b0), "r"(b1));
}

__device__ __forceinline__ void cpa16(unsigned dst, const void* src) {
    asm volatile("cp.async.cg.shared.global [%0], [%1], 16;" :: "r"(dst), "l"(src));
}
__device__ __forceinline__ void cpcommit() { asm volatile("cp.async.commit_group;"); }
template<int N> __device__ __forceinline__ void cpwait() {
    asm volatile("cp.async.wait_group %0;" :: "n"(N));
}

// -------------------- block reductions (256 threads) -----------------------
__device__ __forceinline__ float blk_sum(float v) {
    __shared__ float sh[32];
    int lane = threadIdx.x & 31, w = threadIdx.x >> 5;
    #pragma unroll
    for (int o = 16; o; o >>= 1) v += __shfl_xor_sync(0xffffffffu, v, o);
    if (lane == 0) sh[w] = v;
    __syncthreads();
    if (w == 0) {
        v = (lane < 8) ? sh[lane] : 0.0f;
        #pragma unroll
        for (int o = 4; o; o >>= 1) v += __shfl_xor_sync(0xffffffffu, v, o);
        if (lane == 0) sh[0] = v;
    }
    __syncthreads();
    v = sh[0];
    __syncthreads();
    return v;
}

__device__ __forceinline__ float blk_max(float v) {
    __shared__ float sh[32];
    int lane = threadIdx.x & 31, w = threadIdx.x >> 5;
    #pragma unroll
    for (int o = 16; o; o >>= 1) v = fmaxf(v, __shfl_xor_sync(0xffffffffu, v, o));
    if (lane == 0) sh[w] = v;
    __syncthreads();
    if (w == 0) {
        v = (lane < 8) ? sh[lane] : -INFINITY;
        #pragma unroll
        for (int o = 4; o; o >>= 1) v = fmaxf(v, __shfl_xor_sync(0xffffffffu, v, o));
        if (lane == 0) sh[0] = v;
    }
    __syncthreads();
    v = sh[0];
    __syncthreads();
    return v;
}

// -------------------- LayerNorm (bf16 hi/lo out or fp32 out) ---------------
template<bool BFOUT>
__global__ void ln_k(const float* __restrict__ x, const float* __restrict__ g,
                     const float* __restrict__ b, float* __restrict__ of,
                     bf16* __restrict__ ohi, bf16* __restrict__ olo) {
    long row = blockIdx.x;
    float4 v = ((const float4*)(x + row * DIMM))[threadIdx.x];
    float mu = blk_sum(v.x + v.y + v.z + v.w) * (1.0f / DIMM);
    float dx = v.x - mu, dy = v.y - mu, dz = v.z - mu, dw = v.w - mu;
    float var = blk_sum(dx*dx + dy*dy + dz*dz + dw*dw) * (1.0f / DIMM);
    float inv = rsqrtf(var + 1e-5f);
    float4 gg = ((const float4*)g)[threadIdx.x];
    float4 bb = ((const float4*)b)[threadIdx.x];
    float r0 = dx*inv*gg.x + bb.x, r1 = dy*inv*gg.y + bb.y;
    float r2 = dz*inv*gg.z + bb.z, r3 = dw*inv*gg.w + bb.w;
    if (BFOUT) {
        bf16 h0,l0,h1,l1,h2,l2,h3,l3;
        bsplit(r0,h0,l0); bsplit(r1,h1,l1); bsplit(r2,h2,l2); bsplit(r3,h3,l3);
        bf162 a; a.x=h0; a.y=h1; bf162 c; c.x=h2; c.y=h3;
        ((bf162*)(ohi + row*DIMM))[threadIdx.x*2]   = a;
        ((bf162*)(ohi + row*DIMM))[threadIdx.x*2+1] = c;
        a.x=l0; a.y=l1; c.x=l2; c.y=l3;
        ((bf162*)(olo + row*DIMM))[threadIdx.x*2]   = a;
        ((bf162*)(olo + row*DIMM))[threadIdx.x*2+1] = c;
    } else {
        float4 r; r.x=r0; r.y=r1; r.z=r2; r.w=r3;
        ((float4*)(of + row*DIMM))[threadIdx.x] = r;
    }
}

// -------------------- softmax -> bf16 hi/lo --------------------------------
__global__ void softmax_k(const float* __restrict__ s, bf16* __restrict__ ohi,
                          bf16* __restrict__ olo) {
    long row = blockIdx.x;
    float4 v = ((const float4*)(s + row * TT))[threadIdx.x];
    float m = blk_max(fmaxf(fmaxf(v.x, v.y), fmaxf(v.z, v.w)));
    v.x = expf(v.x-m); v.y = expf(v.y-m); v.z = expf(v.z-m); v.w = expf(v.w-m);
    float inv = 1.0f / blk_sum(v.x + v.y + v.z + v.w);
    v.x *= inv; v.y *= inv; v.z *= inv; v.w *= inv;
    bf16 h0,l0,h1,l1,h2,l2,h3,l3;
    bsplit(v.x,h0,l0); bsplit(v.y,h1,l1); bsplit(v.z,h2,l2); bsplit(v.w,h3,l3);
    bf162 a; a.x=h0; a.y=h1; bf162 c; c.x=h2; c.y=h3;
    ((bf162*)(ohi + row*TT))[threadIdx.x*2]   = a;
    ((bf162*)(ohi + row*TT))[threadIdx.x*2+1] = c;
    a.x=l0; a.y=l1; c.x=l2; c.y=l3;
    ((bf162*)(olo + row*TT))[threadIdx.x*2]   = a;
    ((bf162*)(olo + row*TT))[threadIdx.x*2+1] = c;
}

// -------------------- weight transpose+split: W[K][N] -> [N][K] hi/lo ------
__global__ void wconv(const float* __restrict__ W, bf16* __restrict__ hi,
                      bf16* __restrict__ lo, int K, int N) {
    __shared__ float t[32][33];
    int k0 = blockIdx.y * 32, n0 = blockIdx.x * 32;
    int tx = threadIdx.x & 31, ty = threadIdx.x >> 5;
    #pragma unroll
    for (int r = 0; r < 4; r++)
        t[ty + r*8][tx] = W[(long)(k0 + ty + r*8) * N + n0 + tx];
    __syncthreads();
    #pragma unroll
    for (int r = 0; r < 4; r++) {
        float v = t[tx][ty + r*8];
        long o = (long)(n0 + ty + r*8) * K + k0 + tx;
        bf16 h, l; bsplit(v, h, l);
        hi[o] = h; lo[o] = l;
    }
}

// -------------------- elementwise fp32 -> bf16 hi/lo -----------------------
__global__ void fconv(const float* __restrict__ s, bf16* __restrict__ hi,
                      bf16* __restrict__ lo) {
    long i = (long)blockIdx.x * blockDim.x + threadIdx.x;
    float4 v = ((const float4*)s)[i];
    bf16 h0,l0,h1,l1,h2,l2,h3,l3;
    bsplit(v.x,h0,l0); bsplit(v.y,h1,l1); bsplit(v.z,h2,l2); bsplit(v.w,h3,l3);
    bf162 a; a.x=h0; a.y=h1; bf162 c; c.x=h2; c.y=h3;
    ((bf162*)hi)[i*2] = a; ((bf162*)hi)[i*2+1] = c;
    a.x=l0; a.y=l1; c.x=l2; c.y=l3;
    ((bf162*)lo)[i*2] = a; ((bf162*)lo)[i*2+1] = c;
}

// -------------------- pack scale*[q|qb], [k|kb] per head -------------------
__global__ void pack_qk(const float* __restrict__ qkv, const float* __restrict__ qkvb,
                        bf16* __restrict__ qhi, bf16* __restrict__ qlo,
                        bf16* __restrict__ khi, bf16* __restrict__ klo, float scale) {
    int idx = blockIdx.x * blockDim.x + threadIdx.x;   // NBH*TT*128
    int d  = idx & 127;
    int i  = (idx >> 7) & (TT - 1);
    int bh = idx >> 17;
    int b = bh >> 4, h = bh & 15;
    long tok = (long)b * TT + i;
    float q, k;
    if (d < 64) {
        q = qkv[tok * 3072 + h * 64 + d];
        k = qkv[tok * 3072 + INNER + h * 64 + d];
    } else {
        q = qkvb[tok * 2048 + h * 64 + (d - 64)];
        k = qkvb[tok * 2048 + INNER + h * 64 + (d - 64)];
    }
    bf16 hh, ll;
    bsplit(q * scale, hh, ll);  qhi[idx] = hh; qlo[idx] = ll;
    bsplit(k, hh, ll);          khi[idx] = hh; klo[idx] = ll;
}

// -------------------- V transpose: qkv V part -> [bh][d][t] hi/lo ----------
__global__ void vconv(const float* __restrict__ qkv, bf16* __restrict__ vhi,
                      bf16* __restrict__ vlo) {
    __shared__ float t[32][33];
    int i0 = blockIdx.x * 32, d0 = blockIdx.y * 32, bh = blockIdx.z;
    int b = bh >> 4, h = bh & 15;
    int tx = threadIdx.x & 31, ty = threadIdx.x >> 5;
    #pragma unroll
    for (int r = 0; r < 4; r++)
        t[ty + r*8][tx] = qkv[(long)(b*TT + i0 + ty + r*8) * 3072 + 2048 + h*64 + d0 + tx];
    __syncthreads();
    #pragma unroll
    for (int r = 0; r < 4; r++) {
        float v = t[tx][ty + r*8];
        long o = (long)(bh*64 + d0 + ty + r*8) * TT + i0 + tx;
        bf16 hh, ll; bsplit(v, hh, ll);
        vhi[o] = hh; vlo[o] = ll;
    }
}

// -------------------- bf16x3 tensor-core GEMM ------------------------------
// C[m,n] = sum_k A[m,k]*B[n,k] with A,B given as (hi,lo) bf16 pairs, [row][k].
// EPI: 0 plain fp32; 1 fp32 + bias[n] + resid; 2 gelu(+bias)->bf16 pair;
//      3 plain ->bf16 pair.
template<int BM, int BN, int WX, int WY, int EPI>
__global__ void __launch_bounds__(WX*WY*32) bgemm(
    const bf16* __restrict__ Ahi, const bf16* __restrict__ Alo,
    const bf16* __restrict__ Bhi, const bf16* __restrict__ Blo,
    float* __restrict__ C, bf16* __restrict__ Chi, bf16* __restrict__ Clo,
    int lda, int ldb, int ldc, int K,
    long sAb, long sAh, long sBb, long sBh, long sCb, long sCh,
    const float* __restrict__ bias, const float* __restrict__ resid, int ldr)
{
    constexpr int NT  = WX * WY * 32;
    constexpr int WTM = BM / WY, WTN = BN / WX;
    constexpr int MF  = WTM / 16, NF = WTN / 8, NP = NF / 2;
    constexpr int SZA = BM * 128, SZB = BN * 128;   // bytes per (buf,half)

    extern __shared__ __align__(128) char dsm[];
    const unsigned sb  = (unsigned)__cvta_generic_to_shared(dsm);
    const unsigned aHiB = sb, aLoB = sb + 2*SZA;
    const unsigned bHiB = sb + 4*SZA, bLoB = sb + 4*SZA + 2*SZB;

    const int z = blockIdx.z;
    const bf16* Ah = Ahi + (long)(z >> 4) * sAb + (long)(z & 15) * sAh;
    const bf16* Al = Alo + (long)(z >> 4) * sAb + (long)(z & 15) * sAh;
    const bf16* Bh = Bhi + (long)(z >> 4) * sBb + (long)(z & 15) * sBh;
    const bf16* Bl = Blo + (long)(z >> 4) * sBb + (long)(z & 15) * sBh;
    const long  coff = (long)(z >> 4) * sCb + (long)(z & 15) * sCh;

    const int bm0 = blockIdx.y * BM, bn0 = blockIdx.x * BN;
    const int tid = threadIdx.x, lane = tid & 31, wid = tid >> 5;
    const int wm = (wid / WX) * WTM, wn = (wid % WX) * WTN;
    const int lr = lane & 15, h8 = lane >> 4;

    float acc[MF][NF][4];
    #pragma unroll
    for (int a = 0; a < MF; a++)
        #pragma unroll
        for (int b = 0; b < NF; b++)
            #pragma unroll
            for (int c = 0; c < 4; c++) acc[a][b][c] = 0.0f;

    auto loadTiles = [&](int k0, int buf) {
        #pragma unroll 2
        for (int t = tid; t < BM * 8; t += NT) {
            int r = t >> 3, c = t & 7;
            long go = (long)(bm0 + r) * lda + k0 + c * 8;
            unsigned so = (unsigned)(((r << 3) + (c ^ (r & 7))) << 4);
            cpa16(aHiB + buf * SZA + so, Ah + go);
            cpa16(aLoB + buf * SZA + so, Al + go);
        }
        #pragma unroll 2
        for (int t = tid; t < BN * 8; t += NT) {
            int r = t >> 3, c = t & 7;
            long go = (long)(bn0 + r) * ldb + k0 + c * 8;
            unsigned so = (unsigned)(((r << 3) + (c ^ (r & 7))) << 4);
            cpa16(bHiB + buf * SZB + so, Bh + go);
            cpa16(bLoB + buf * SZB + so, Bl + go);
        }
    };

    auto comp = [&](int buf) {
        const unsigned aH = aHiB + buf * SZA, aL = aLoB + buf * SZA;
        const unsigned bH = bHiB + buf * SZB, bL = bLoB + buf * SZB;
        #pragma unroll
        for (int ks = 0; ks < 4; ks++) {
            unsigned AH[MF][4], AL[MF][4], BH[NP][4], BL[NP][4];
            #pragma unroll
            for (int mf = 0; mf < MF; mf++) {
                int row = wm + mf * 16 + lr;
                unsigned off = (unsigned)(((row << 3) + ((ks*2 + h8) ^ (row & 7))) << 4);
                ldm4(AH[mf][0], AH[mf][1], AH[mf][2], AH[mf][3], aH + off);
                ldm4(AL[mf][0], AL[mf][1], AL[mf][2], AL[mf][3], aL + off);
            }
            #pragma unroll
            for (int p = 0; p < NP; p++) {
                int row = wn + p * 16 + lr;
                unsigned off = (unsigned)(((row << 3) + ((ks*2 + h8) ^ (row & 7))) << 4);
                ldm4(BH[p][0], BH[p][1], BH[p][2], BH[p][3], bH + off);
                ldm4(BL[p][0], BL[p][1], BL[p][2], BL[p][3], bL + off);
            }
            #pragma unroll
            for (int mf = 0; mf < MF; mf++)
                #pragma unroll
                for (int p = 0; p < NP; p++) {
                    mma16816(acc[mf][2*p],   AH[mf], BH[p][0], BH[p][2]);
                    mma16816(acc[mf][2*p],   AH[mf], BL[p][0], BL[p][2]);
                    mma16816(acc[mf][2*p],   AL[mf], BH[p][0], BH[p][2]);
                    mma16816(acc[mf][2*p+1], AH[mf], BH[p][1], BH[p][3]);
                    mma16816(acc[mf][2*p+1], AH[mf], BL[p][1], BL[p][3]);
                    mma16816(acc[mf][2*p+1], AL[mf], BH[p][1], BH[p][3]);
                }
        }
    };

    loadTiles(0, 0); cpcommit();
    const int nk = K >> 6;
    for (int kt = 0; kt < nk; kt++) {
        int buf = kt & 1;
        if (kt + 1 < nk) { loadTiles((kt + 1) << 6, buf ^ 1); cpcommit(); cpwait<1>(); }
        else             { cpwait<0>(); }
        __syncthreads();
        comp(buf);
        __syncthreads();
    }

    // epilogue
    #pragma unroll
    for (int mf = 0; mf < MF; mf++)
        #pragma unroll
        for (int nf = 0; nf < NF; nf++)
            #pragma unroll
            for (int r = 0; r < 2; r++) {
                int m = bm0 + wm + mf * 16 + (lane >> 2) + r * 8;
                int n = bn0 + wn + nf * 8 + (lane & 3) * 2;
                float v0 = acc[mf][nf][r*2], v1 = acc[mf][nf][r*2+1];
                long o = coff + (long)m * ldc + n;
                if constexpr (EPI == 0) {
                    float2 w; w.x = v0; w.y = v1;
                    *(float2*)&C[o] = w;
                } else if constexpr (EPI == 1) {
                    float2 w;
                    w.x = v0 + bias[n] + resid[(long)m * ldr + n];
                    w.y = v1 + bias[n+1] + resid[(long)m * ldr + n + 1];
                    *(float2*)&C[o] = w;
                } else {
                    if constexpr (EPI == 2) {
                        v0 = gelu_f(v0 + bias[n]);
                        v1 = gelu_f(v1 + bias[n+1]);
                    }
                    bf16 h0,l0,h1,l1;
                    bsplit(v0,h0,l0); bsplit(v1,h1,l1);
                    bf162 hh; hh.x=h0; hh.y=h1;
                    bf162 ll; ll.x=l0; ll.y=l1;
                    *(bf162*)&Chi[o] = hh;
                    *(bf162*)&Clo[o] = ll;
                }
            }
}

// -------------------- host orchestration -----------------------------------
#define SMB(BM,BN) ((BM + BN) * 512)

extern "C" void kernel_launch(void* const* d_in, const int* in_sizes, int n_in,
                              void* d_out, int out_size) {
    (void)in_sizes; (void)n_in; (void)out_size;
    const float* x    = (const float*)d_in[0];
    const float* bias = (const float*)d_in[1];
    const float* wqkv = (const float*)d_in[2];
    const float* wout = (const float*)d_in[3];
    const float* bout = (const float*)d_in[4];
    const float* ln1g = (const float*)d_in[5];
    const float* ln1b = (const float*)d_in[6];
    const float* w1   = (const float*)d_in[7];
    const float* b1   = (const float*)d_in[8];
    const float* w2   = (const float*)d_in[9];
    const float* b2   = (const float*)d_in[10];
    const float* ln2g = (const float*)d_in[11];
    const float* ln2b = (const float*)d_in[12];
    const float* lnfg = (const float*)d_in[13];
    const float* lnfb = (const float*)d_in[14];

    float *px, *pqkv, *pqkvb, *psc;
    bf16 *phh, *phl, *pbh, *pbl, *pqh, *pql, *pkh, *pkl, *pvh, *pvl;
    bf16 *psh, *psl, *paoh, *paol, *pfh, *pfl;
    bf16 *pwqh, *pwql, *pwoh, *pwol, *pw1h, *pw1l, *pw2h, *pw2l;
    cudaGetSymbolAddress((void**)&px,    g_x);
    cudaGetSymbolAddress((void**)&pqkv,  g_qkv);
    cudaGetSymbolAddress((void**)&pqkvb, g_qkvb);
    cudaGetSymbolAddress((void**)&psc,   g_sc);
    cudaGetSymbolAddress((void**)&phh,   g_h_hi);   cudaGetSymbolAddress((void**)&phl, g_h_lo);
    cudaGetSymbolAddress((void**)&pbh,   g_bias_hi); cudaGetSymbolAddress((void**)&pbl, g_bias_lo);
    cudaGetSymbolAddress((void**)&pqh,   g_QQ_hi);  cudaGetSymbolAddress((void**)&pql, g_QQ_lo);
    cudaGetSymbolAddress((void**)&pkh,   g_KK_hi);  cudaGetSymbolAddress((void**)&pkl, g_KK_lo);
    cudaGetSymbolAddress((void**)&pvh,   g_VT_hi);  cudaGetSymbolAddress((void**)&pvl, g_VT_lo);
    cudaGetSymbolAddress((void**)&psh,   g_scb_hi); cudaGetSymbolAddress((void**)&psl, g_scb_lo);
    cudaGetSymbolAddress((void**)&paoh,  g_ao_hi);  cudaGetSymbolAddress((void**)&paol, g_ao_lo);
    cudaGetSymbolAddress((void**)&pfh,   g_ff_hi);  cudaGetSymbolAddress((void**)&pfl, g_ff_lo);
    cudaGetSymbolAddress((void**)&pwqh,  g_wqkvT_hi); cudaGetSymbolAddress((void**)&pwql, g_wqkvT_lo);
    cudaGetSymbolAddress((void**)&pwoh,  g_woutT_hi); cudaGetSymbolAddress((void**)&pwol, g_woutT_lo);
    cudaGetSymbolAddress((void**)&pw1h,  g_w1T_hi);  cudaGetSymbolAddress((void**)&pw1l, g_w1T_lo);
    cudaGetSymbolAddress((void**)&pw2h,  g_w2T_hi);  cudaGetSymbolAddress((void**)&pw2l, g_w2T_lo);

    cudaFuncSetAttribute(bgemm<128,128,4,2,0>, cudaFuncAttributeMaxDynamicSharedMemorySize, SMB(128,128));
    cudaFuncSetAttribute(bgemm<128,128,4,2,1>, cudaFuncAttributeMaxDynamicSharedMemorySize, SMB(128,128));
    cudaFuncSetAttribute(bgemm<128,128,4,2,2>, cudaFuncAttributeMaxDynamicSharedMemorySize, SMB(128,128));
    cudaFuncSetAttribute(bgemm<128,64,2,2,3>,  cudaFuncAttributeMaxDynamicSharedMemorySize, SMB(128,64));

    cudaMemcpyAsync(px, x, sizeof(float) * MTOK * DIMM, cudaMemcpyDeviceToDevice);

    // one-time conversions
    fconv<<<MTOK*DIMM/1024, 256>>>(bias, pbh, pbl);
    for (int l = 0; l < DEPTH; l++) {
        wconv<<<dim3(3072/32, 1024/32), 256>>>(wqkv + (long)l*1024*3072, pwqh + (long)l*3072*1024, pwql + (long)l*3072*1024, 1024, 3072);
        wconv<<<dim3(1024/32, 1024/32), 256>>>(wout + (long)l*1024*1024, pwoh + (long)l*1024*1024, pwol + (long)l*1024*1024, 1024, 1024);
        wconv<<<dim3(4096/32, 1024/32), 256>>>(w1   + (long)l*1024*4096, pw1h + (long)l*4096*1024, pw1l + (long)l*4096*1024, 1024, 4096);
        wconv<<<dim3(1024/32, 4096/32), 256>>>(w2   + (long)l*4096*1024, pw2h + (long)l*1024*4096, pw2l + (long)l*1024*4096, 4096, 1024);
    }

    const float scale = 0.125f;

    for (int l = 0; l < DEPTH; l++) {
        bf16 *wqh = pwqh + (long)l*3072*1024, *wql = pwql + (long)l*3072*1024;
        bf16 *woh = pwoh + (long)l*1024*1024, *wol = pwol + (long)l*1024*1024;
        bf16 *w1h = pw1h + (long)l*4096*1024, *w1l = pw1l + (long)l*4096*1024;
        bf16 *w2h = pw2h + (long)l*1024*4096, *w2l = pw2l + (long)l*1024*4096;

        // LN1 -> bf16 h
        ln_k<true><<<MTOK, 256>>>(px, ln1g + l*DIMM, ln1b + l*DIMM, nullptr, phh, phl);

        // qkv = h @ Wqkv  (M4096 N3072 K1024)
        bgemm<128,128,4,2,0><<<dim3(24, 32, 1), 256, SMB(128,128)>>>(
            phh, phl, wqh, wql, pqkv, nullptr, nullptr,
            1024, 1024, 3072, 1024, 0,0,0,0,0,0, nullptr, nullptr, 0);

        // qkvb = bias @ Wqkv[:, :2048]  (N2048)
        bgemm<128,128,4,2,0><<<dim3(16, 32, 1), 256, SMB(128,128)>>>(
            pbh, pbl, wqh, wql, pqkvb, nullptr, nullptr,
            1024, 1024, 2048, 1024, 0,0,0,0,0,0, nullptr, nullptr, 0);

        pack_qk<<<(NBH*TT*128)/256, 256>>>(pqkv, pqkvb, pqh, pql, pkh, pkl, scale);
        vconv<<<dim3(32, 2, NBH), 256>>>(pqkv, pvh, pvl);

        // scores = QQ @ KK^T per head (M1024 N1024 K128, batch 64)
        bgemm<128,128,4,2,0><<<dim3(8, 8, NBH), 256, SMB(128,128)>>>(
            pqh, pql, pkh, pkl, psc, nullptr, nullptr,
            128, 128, 1024, 128,
            (long)16*TT*128, (long)TT*128, (long)16*TT*128, (long)TT*128,
            (long)16*TT*TT, (long)TT*TT, nullptr, nullptr, 0);

        softmax_k<<<NBH*TT, 256>>>(psc, psh, psl);

        // ao = P @ V per head (M1024 N64 K1024, batch 64) -> bf16 ao
        bgemm<128,64,2,2,3><<<dim3(1, 8, NBH), 128, SMB(128,64)>>>(
            psh, psl, pvh, pvl, nullptr, paoh, paol,
            1024, 1024, 1024, 1024,
            (long)16*TT*TT, (long)TT*TT, (long)16*64*TT, (long)64*TT,
            (long)TT*INNER, 64L, nullptr, nullptr, 0);

        // x = x + ao @ Wout + bout
        bgemm<128,128,4,2,1><<<dim3(8, 32, 1), 256, SMB(128,128)>>>(
            paoh, paol, woh, wol, px, nullptr, nullptr,
            1024, 1024, 1024, 1024, 0,0,0,0,0,0, bout + l*DIMM, px, 1024);

        // LN2 -> bf16 h
        ln_k<true><<<MTOK, 256>>>(px, ln2g + l*DIMM, ln2b + l*DIMM, nullptr, phh, phl);

        // ff = gelu(h @ W1 + b1) -> bf16
        bgemm<128,128,4,2,2><<<dim3(32, 32, 1), 256, SMB(128,128)>>>(
            phh, phl, w1h, w1l, nullptr, pfh, pfl,
            1024, 1024, 4096, 1024, 0,0,0,0,0,0, b1 + l*FFI, nullptr, 0);

        // x = x + ff @ W2 + b2
        bgemm<128,128,4,2,1><<<dim3(8, 32, 1), 256, SMB(128,128)>>>(
            pfh, pfl, w2h, w2l, px, nullptr, nullptr,
            4096, 4096, 1024, 4096, 0,0,0,0,0,0, b2 + l*DIMM, px, 1024);
    }

    // final LN -> fp32 out
    ln_k<false><<<MTOK, 256>>>(px, lnfg, lnfb, (float*)d_out, nullptr, nullptr);
}

// round 6
// speedup vs baseline: 2.5310x; 1.0816x over previous
#include <cuda_runtime.h>
#include <cuda_bf16.h>
#include <math.h>

// ---------------------------------------------------------------------------
// TemporalTransformer forward. Dense GEMMs: bf16x3 split on mma.sync tensor
// cores. Attention: fused flash kernel (QK^T + online softmax + PV), scores
// never materialized.
// ---------------------------------------------------------------------------

#define DIMM   1024
#define DEPTH  4
#define HEADS  16
#define INNER  1024
#define FFI    4096
#define BB     4
#define TT     1024
#define MTOK   (BB*TT)
#define NBH    (BB*HEADS)

typedef __nv_bfloat16 bf16;
typedef __nv_bfloat162 bf162;

// -------------------- device-global scratch --------------------------------
__device__ float g_x   [MTOK*DIMM];
__device__ float g_qkv [MTOK*3*INNER];
__device__ float g_qkvb[MTOK*2*INNER];

__device__ bf16 g_h_hi [MTOK*DIMM],      g_h_lo [MTOK*DIMM];
__device__ bf16 g_bias_hi[MTOK*DIMM],    g_bias_lo[MTOK*DIMM];
__device__ bf16 g_QQ_hi[NBH*TT*128],     g_QQ_lo[NBH*TT*128];
__device__ bf16 g_KK_hi[NBH*TT*128],     g_KK_lo[NBH*TT*128];
__device__ bf16 g_VT_hi[NBH*64*TT],      g_VT_lo[NBH*64*TT];
__device__ bf16 g_ao_hi[MTOK*INNER],     g_ao_lo[MTOK*INNER];
__device__ bf16 g_ff_hi[(long)MTOK*FFI], g_ff_lo[(long)MTOK*FFI];
__device__ bf16 g_wqkvT_hi[DEPTH*3072*1024], g_wqkvT_lo[DEPTH*3072*1024];
__device__ bf16 g_woutT_hi[DEPTH*1024*1024], g_woutT_lo[DEPTH*1024*1024];
__device__ bf16 g_w1T_hi [DEPTH*4096*1024], g_w1T_lo [DEPTH*4096*1024];
__device__ bf16 g_w2T_hi [DEPTH*1024*4096], g_w2T_lo [DEPTH*1024*4096];

// -------------------- helpers ----------------------------------------------
__device__ __forceinline__ bf162 mk2(bf16 a, bf16 b) {
    bf162 t; t.x = a; t.y = b; return t;
}

__device__ __forceinline__ void bsplit(float v, bf16& h, bf16& l) {
    bf16 hb = __float2bfloat16_rz(v);
    h = hb;
    l = __float2bfloat16(v - __bfloat162float(hb));
}

__device__ __forceinline__ unsigned pk2(bf16 a, bf16 b) {
    bf162 t; t.x = a; t.y = b;
    return *(unsigned*)&t;
}

__device__ __forceinline__ float gelu_f(float x) {
    return 0.5f * x * (1.0f + erff(x * 0.70710678118654752440f));
}

__device__ __forceinline__ void ldm4(unsigned& r0, unsigned& r1, unsigned& r2,
                                     unsigned& r3, unsigned a) {
    asm volatile("ldmatrix.sync.aligned.m8n8.x4.shared.b16 {%0,%1,%2,%3}, [%4];"
                 : "=r"(r0), "=r"(r1), "=r"(r2), "=r"(r3) : "r"(a));
}

__device__ __forceinline__ void mma16816(float* d, const unsigned* a,
                                         unsigned b0, unsigned b1) {
    asm volatile(
        "mma.sync.aligned.m16n8k16.row.col.f32.bf16.bf16.f32 "
        "{%0,%1,%2,%3}, {%4,%5,%6,%7}, {%8,%9}, {%0,%1,%2,%3};"
        : "+f"(d[0]), "+f"(d[1]), "+f"(d[2]), "+f"(d[3])
        : "r"(a[0]), "r"(a[1]), "r"(a[2]), "r"(a[3]), "r"(b0), "r"(b1));
}

__device__ __forceinline__ void cpa16(unsigned dst, const void* src) {
    asm volatile("cp.async.cg.shared.global [%0], [%1], 16;" :: "r"(dst), "l"(src));
}
__device__ __forceinline__ void cpcommit() { asm volatile("cp.async.commit_group;"); }
template<int N> __device__ __forceinline__ void cpwait() {
    asm volatile("cp.async.wait_group %0;" :: "n"(N));
}

// -------------------- block reductions (256 threads) -----------------------
__device__ __forceinline__ float blk_sum(float v) {
    __shared__ float sh[32];
    int lane = threadIdx.x & 31, w = threadIdx.x >> 5;
    #pragma unroll
    for (int o = 16; o; o >>= 1) v += __shfl_xor_sync(0xffffffffu, v, o);
    if (lane == 0) sh[w] = v;
    __syncthreads();
    if (w == 0) {
        v = (lane < 8) ? sh[lane] : 0.0f;
        #pragma unroll
        for (int o = 4; o; o >>= 1) v += __shfl_xor_sync(0xffffffffu, v, o);
        if (lane == 0) sh[0] = v;
    }
    __syncthreads();
    v = sh[0];
    __syncthreads();
    return v;
}

// -------------------- LayerNorm --------------------------------------------
template<bool BFOUT>
__global__ void ln_k(const float* __restrict__ x, const float* __restrict__ g,
                     const float* __restrict__ b, float* __restrict__ of,
                     bf16* __restrict__ ohi, bf16* __restrict__ olo) {
    long row = blockIdx.x;
    float4 v = ((const float4*)(x + row * DIMM))[threadIdx.x];
    float mu = blk_sum(v.x + v.y + v.z + v.w) * (1.0f / DIMM);
    float dx = v.x - mu, dy = v.y - mu, dz = v.z - mu, dw = v.w - mu;
    float var = blk_sum(dx*dx + dy*dy + dz*dz + dw*dw) * (1.0f / DIMM);
    float inv = rsqrtf(var + 1e-5f);
    float4 gg = ((const float4*)g)[threadIdx.x];
    float4 bb = ((const float4*)b)[threadIdx.x];
    float r0 = dx*inv*gg.x + bb.x, r1 = dy*inv*gg.y + bb.y;
    float r2 = dz*inv*gg.z + bb.z, r3 = dw*inv*gg.w + bb.w;
    if (BFOUT) {
        bf16 h0,l0,h1,l1,h2,l2,h3,l3;
        bsplit(r0,h0,l0); bsplit(r1,h1,l1); bsplit(r2,h2,l2); bsplit(r3,h3,l3);
        ((bf162*)(ohi + row*DIMM))[threadIdx.x*2]   = mk2(h0,h1);
        ((bf162*)(ohi + row*DIMM))[threadIdx.x*2+1] = mk2(h2,h3);
        ((bf162*)(olo + row*DIMM))[threadIdx.x*2]   = mk2(l0,l1);
        ((bf162*)(olo + row*DIMM))[threadIdx.x*2+1] = mk2(l2,l3);
    } else {
        float4 r; r.x=r0; r.y=r1; r.z=r2; r.w=r3;
        ((float4*)(of + row*DIMM))[threadIdx.x] = r;
    }
}

// -------------------- weight transpose+split: W[K][N] -> [N][K] hi/lo ------
__global__ void wconv(const float* __restrict__ W, bf16* __restrict__ hi,
                      bf16* __restrict__ lo, int K, int N) {
    __shared__ float t[32][33];
    int k0 = blockIdx.y * 32, n0 = blockIdx.x * 32;
    int tx = threadIdx.x & 31, ty = threadIdx.x >> 5;
    #pragma unroll
    for (int r = 0; r < 4; r++)
        t[ty + r*8][tx] = W[(long)(k0 + ty + r*8) * N + n0 + tx];
    __syncthreads();
    #pragma unroll
    for (int r = 0; r < 4; r++) {
        float v = t[tx][ty + r*8];
        long o = (long)(n0 + ty + r*8) * K + k0 + tx;
        bf16 h, l; bsplit(v, h, l);
        hi[o] = h; lo[o] = l;
    }
}

// -------------------- elementwise fp32 -> bf16 hi/lo -----------------------
__global__ void fconv(const float* __restrict__ s, bf16* __restrict__ hi,
                      bf16* __restrict__ lo) {
    long i = (long)blockIdx.x * blockDim.x + threadIdx.x;
    float4 v = ((const float4*)s)[i];
    bf16 h0,l0,h1,l1,h2,l2,h3,l3;
    bsplit(v.x,h0,l0); bsplit(v.y,h1,l1); bsplit(v.z,h2,l2); bsplit(v.w,h3,l3);
    ((bf162*)hi)[i*2]   = mk2(h0,h1);
    ((bf162*)hi)[i*2+1] = mk2(h2,h3);
    ((bf162*)lo)[i*2]   = mk2(l0,l1);
    ((bf162*)lo)[i*2+1] = mk2(l2,l3);
}

// -------------------- pack scale*[q|qb], [k|kb] per head -------------------
__global__ void pack_qk(const float* __restrict__ qkv, const float* __restrict__ qkvb,
                        bf16* __restrict__ qhi, bf16* __restrict__ qlo,
                        bf16* __restrict__ khi, bf16* __restrict__ klo, float scale) {
    int idx = blockIdx.x * blockDim.x + threadIdx.x;   // NBH*TT*128
    int d  = idx & 127;
    int i  = (idx >> 7) & (TT - 1);
    int bh = idx >> 17;
    int b = bh >> 4, h = bh & 15;
    long tok = (long)b * TT + i;
    float q, k;
    if (d < 64) {
        q = qkv[tok * 3072 + h * 64 + d];
        k = qkv[tok * 3072 + INNER + h * 64 + d];
    } else {
        q = qkvb[tok * 2048 + h * 64 + (d - 64)];
        k = qkvb[tok * 2048 + INNER + h * 64 + (d - 64)];
    }
    bf16 hh, ll;
    bsplit(q * scale, hh, ll);  qhi[idx] = hh; qlo[idx] = ll;
    bsplit(k, hh, ll);          khi[idx] = hh; klo[idx] = ll;
}

// -------------------- V transpose: qkv V part -> [bh][d][t] hi/lo ----------
__global__ void vconv(const float* __restrict__ qkv, bf16* __restrict__ vhi,
                      bf16* __restrict__ vlo) {
    __shared__ float t[32][33];
    int i0 = blockIdx.x * 32, d0 = blockIdx.y * 32, bh = blockIdx.z;
    int b = bh >> 4, h = bh & 15;
    int tx = threadIdx.x & 31, ty = threadIdx.x >> 5;
    #pragma unroll
    for (int r = 0; r < 4; r++)
        t[ty + r*8][tx] = qkv[(long)(b*TT + i0 + ty + r*8) * 3072 + 2048 + h*64 + d0 + tx];
    __syncthreads();
    #pragma unroll
    for (int r = 0; r < 4; r++) {
        float v = t[tx][ty + r*8];
        long o = (long)(bh*64 + d0 + ty + r*8) * TT + i0 + tx;
        bf16 hh, ll; bsplit(v, hh, ll);
        vhi[o] = hh; vlo[o] = ll;
    }
}

// -------------------- fused flash attention --------------------------------
// Per block: one bh, 128 q-rows. Q'[128x128] in smem; loop 8 key tiles:
// S = Q'K'^T (bf16x3), online softmax in fp32 regs, O += P V (bf16x3).
// Tiles in smem: row-major, 16 chunks of 16B per row, chunk c XOR (row&7).
#define FA_SQH 0
#define FA_SQL 32768
#define FA_SKH 65536
#define FA_SKL 98304
#define FA_SVH 131072
#define FA_SVL 147456
#define FA_SMEM 163840

__global__ void __launch_bounds__(256) flash_k(
    const bf16* __restrict__ Qh, const bf16* __restrict__ Ql,
    const bf16* __restrict__ Kh, const bf16* __restrict__ Kl,
    const bf16* __restrict__ Vh, const bf16* __restrict__ Vl,
    bf16* __restrict__ Ohi, bf16* __restrict__ Olo)
{
    extern __shared__ __align__(128) char fsm[];
    const unsigned sb = (unsigned)__cvta_generic_to_shared(fsm);

    const int mt = blockIdx.x, bh = blockIdx.y;
    const int m0 = mt * 128;
    const int tid = threadIdx.x, lane = tid & 31, wid = tid >> 5;
    const int wm = wid * 16;               // 8 warps x 16 rows
    const int lr = lane & 15, h8 = lane >> 4;

    const bf16* Qhp = Qh + ((long)bh * TT + m0) * 128;
    const bf16* Qlp = Ql + ((long)bh * TT + m0) * 128;
    const bf16* Khp = Kh + (long)bh * TT * 128;
    const bf16* Klp = Kl + (long)bh * TT * 128;
    const bf16* Vhp = Vh + (long)bh * 64 * TT;
    const bf16* Vlp = Vl + (long)bh * 64 * TT;

    // load Q tile (128 rows x 16 chunks) hi+lo
    #pragma unroll 4
    for (int t = tid; t < 2048; t += 256) {
        int r = t >> 4, c = t & 15;
        long go = (long)r * 128 + c * 8;
        unsigned so = (unsigned)(((r << 4) + (c ^ (r & 7))) << 4);
        cpa16(sb + FA_SQH + so, Qhp + go);
        cpa16(sb + FA_SQL + so, Qlp + go);
    }
    cpcommit();

    float oacc[8][4];
    #pragma unroll
    for (int i = 0; i < 8; i++)
        #pragma unroll
        for (int j = 0; j < 4; j++) oacc[i][j] = 0.0f;
    float mrow0 = -INFINITY, mrow1 = -INFINITY;
    float lrow0 = 0.0f, lrow1 = 0.0f;

    for (int jt = 0; jt < 8; jt++) {
        // load K tile (128 x 16 chunks) and V^T tile (64 x 16 chunks)
        #pragma unroll 4
        for (int t = tid; t < 2048; t += 256) {
            int r = t >> 4, c = t & 15;
            long go = (long)(jt * 128 + r) * 128 + c * 8;
            unsigned so = (unsigned)(((r << 4) + (c ^ (r & 7))) << 4);
            cpa16(sb + FA_SKH + so, Khp + go);
            cpa16(sb + FA_SKL + so, Klp + go);
        }
        #pragma unroll 2
        for (int t = tid; t < 1024; t += 256) {
            int r = t >> 4, c = t & 15;
            long go = (long)r * TT + jt * 128 + c * 8;
            unsigned so = (unsigned)(((r << 4) + (c ^ (r & 7))) << 4);
            cpa16(sb + FA_SVH + so, Vhp + go);
            cpa16(sb + FA_SVL + so, Vlp + go);
        }
        cpcommit();
        cpwait<0>();
        __syncthreads();

        // ---- S = Q' K'^T  (128 contraction, 8 ksteps) ----
        float sacc[16][4];
        #pragma unroll
        for (int i = 0; i < 16; i++)
            #pragma unroll
            for (int j = 0; j < 4; j++) sacc[i][j] = 0.0f;

        #pragma unroll
        for (int ks = 0; ks < 8; ks++) {
            int c = ks * 2 + h8;
            unsigned AH[4], AL[4];
            {
                int row = wm + lr;
                unsigned off = (unsigned)(((row << 4) + (c ^ (row & 7))) << 4);
                ldm4(AH[0], AH[1], AH[2], AH[3], sb + FA_SQH + off);
                ldm4(AL[0], AL[1], AL[2], AL[3], sb + FA_SQL + off);
            }
            #pragma unroll
            for (int p = 0; p < 8; p++) {
                int row = p * 16 + lr;
                unsigned off = (unsigned)(((row << 4) + (c ^ (row & 7))) << 4);
                unsigned BH[4], BL[4];
                ldm4(BH[0], BH[1], BH[2], BH[3], sb + FA_SKH + off);
                ldm4(BL[0], BL[1], BL[2], BL[3], sb + FA_SKL + off);
                mma16816(sacc[2*p],   AH, BH[0], BH[2]);
                mma16816(sacc[2*p],   AH, BL[0], BL[2]);
                mma16816(sacc[2*p],   AL, BH[0], BH[2]);
                mma16816(sacc[2*p+1], AH, BH[1], BH[3]);
                mma16816(sacc[2*p+1], AH, BL[1], BL[3]);
                mma16816(sacc[2*p+1], AL, BH[1], BH[3]);
            }
        }

        // ---- online softmax update ----
        float tm0 = -INFINITY, tm1 = -INFINITY;
        #pragma unroll
        for (int nf = 0; nf < 16; nf++) {
            tm0 = fmaxf(tm0, fmaxf(sacc[nf][0], sacc[nf][1]));
            tm1 = fmaxf(tm1, fmaxf(sacc[nf][2], sacc[nf][3]));
        }
        tm0 = fmaxf(tm0, __shfl_xor_sync(0xffffffffu, tm0, 1));
        tm0 = fmaxf(tm0, __shfl_xor_sync(0xffffffffu, tm0, 2));
        tm1 = fmaxf(tm1, __shfl_xor_sync(0xffffffffu, tm1, 1));
        tm1 = fmaxf(tm1, __shfl_xor_sync(0xffffffffu, tm1, 2));
        float mn0 = fmaxf(mrow0, tm0), mn1 = fmaxf(mrow1, tm1);
        float cor0 = __expf(mrow0 - mn0), cor1 = __expf(mrow1 - mn1);
        mrow0 = mn0; mrow1 = mn1;
        #pragma unroll
        for (int nf = 0; nf < 8; nf++) {
            oacc[nf][0] *= cor0; oacc[nf][1] *= cor0;
            oacc[nf][2] *= cor1; oacc[nf][3] *= cor1;
        }

        // ---- P = exp(S - m), split, and O += P V (per kstep) ----
        float rs0 = 0.0f, rs1 = 0.0f;
        #pragma unroll
        for (int ks = 0; ks < 8; ks++) {
            float p00 = __expf(sacc[2*ks][0]   - mn0);
            float p01 = __expf(sacc[2*ks][1]   - mn0);
            float p02 = __expf(sacc[2*ks][2]   - mn1);
            float p03 = __expf(sacc[2*ks][3]   - mn1);
            float p10 = __expf(sacc[2*ks+1][0] - mn0);
            float p11 = __expf(sacc[2*ks+1][1] - mn0);
            float p12 = __expf(sacc[2*ks+1][2] - mn1);
            float p13 = __expf(sacc[2*ks+1][3] - mn1);
            rs0 += p00 + p01 + p10 + p11;
            rs1 += p02 + p03 + p12 + p13;
            bf16 h, l;
            unsigned PH[4], PL[4];
            bf16 h2, l2;
            bsplit(p00, h, l); bsplit(p01, h2, l2);
            PH[0] = pk2(h, h2); PL[0] = pk2(l, l2);
            bsplit(p02, h, l); bsplit(p03, h2, l2);
            PH[1] = pk2(h, h2); PL[1] = pk2(l, l2);
            bsplit(p10, h, l); bsplit(p11, h2, l2);
            PH[2] = pk2(h, h2); PL[2] = pk2(l, l2);
            bsplit(p12, h, l); bsplit(p13, h2, l2);
            PH[3] = pk2(h, h2); PL[3] = pk2(l, l2);

            int c = ks * 2 + h8;
            #pragma unroll
            for (int p = 0; p < 4; p++) {
                int row = p * 16 + lr;
                unsigned off = (unsigned)(((row << 4) + (c ^ (row & 7))) << 4);
                unsigned BH[4], BL[4];
                ldm4(BH[0], BH[1], BH[2], BH[3], sb + FA_SVH + off);
                ldm4(BL[0], BL[1], BL[2], BL[3], sb + FA_SVL + off);
                mma16816(oacc[2*p],   PH, BH[0], BH[2]);
                mma16816(oacc[2*p],   PH, BL[0], BL[2]);
                mma16816(oacc[2*p],   PL, BH[0], BH[2]);
                mma16816(oacc[2*p+1], PH, BH[1], BH[3]);
                mma16816(oacc[2*p+1], PH, BL[1], BL[3]);
                mma16816(oacc[2*p+1], PL, BH[1], BH[3]);
            }
        }
        rs0 += __shfl_xor_sync(0xffffffffu, rs0, 1);
        rs0 += __shfl_xor_sync(0xffffffffu, rs0, 2);
        rs1 += __shfl_xor_sync(0xffffffffu, rs1, 1);
        rs1 += __shfl_xor_sync(0xffffffffu, rs1, 2);
        lrow0 = lrow0 * cor0 + rs0;
        lrow1 = lrow1 * cor1 + rs1;

        __syncthreads();
    }

    // ---- epilogue: O /= l, split to bf16 hi/lo, write token-major ----
    float inv0 = 1.0f / lrow0, inv1 = 1.0f / lrow1;
    int b = bh >> 4, h = bh & 15;
    int r0 = m0 + wm + (lane >> 2);
    int cb = h * 64 + (lane & 3) * 2;
    bf16* oh0 = Ohi + ((long)(b * TT + r0)) * INNER + cb;
    bf16* ol0 = Olo + ((long)(b * TT + r0)) * INNER + cb;
    bf16* oh1 = oh0 + 8L * INNER;
    bf16* ol1 = ol0 + 8L * INNER;
    #pragma unroll
    for (int nf = 0; nf < 8; nf++) {
        bf16 ha, la, hb2, lb2;
        bsplit(oacc[nf][0] * inv0, ha, la);
        bsplit(oacc[nf][1] * inv0, hb2, lb2);
        *(bf162*)(oh0 + nf * 8) = mk2(ha, hb2);
        *(bf162*)(ol0 + nf * 8) = mk2(la, lb2);
        bsplit(oacc[nf][2] * inv1, ha, la);
        bsplit(oacc[nf][3] * inv1, hb2, lb2);
        *(bf162*)(oh1 + nf * 8) = mk2(ha, hb2);
        *(bf162*)(ol1 + nf * 8) = mk2(la, lb2);
    }
}

// -------------------- bf16x3 tensor-core GEMM ------------------------------
// C[m,n] = sum_k A[m,k]*B[n,k], A/B as (hi,lo) bf16 pairs, [row][k].
// EPI: 0 plain fp32; 1 fp32 + bias[n] + resid; 2 gelu(+bias)->bf16 pair.
template<int BM, int BN, int WX, int WY, int EPI>
__global__ void __launch_bounds__(WX*WY*32) bgemm(
    const bf16* __restrict__ Ahi, const bf16* __restrict__ Alo,
    const bf16* __restrict__ Bhi, const bf16* __restrict__ Blo,
    float* __restrict__ C, bf16* __restrict__ Chi, bf16* __restrict__ Clo,
    int lda, int ldb, int ldc, int K,
    const float* __restrict__ bias, const float* __restrict__ resid, int ldr)
{
    constexpr int NT  = WX * WY * 32;
    constexpr int WTM = BM / WY, WTN = BN / WX;
    constexpr int MF  = WTM / 16, NF = WTN / 8, NP = NF / 2;
    constexpr int SZA = BM * 128, SZB = BN * 128;

    extern __shared__ __align__(128) char dsm[];
    const unsigned sb  = (unsigned)__cvta_generic_to_shared(dsm);
    const unsigned aHiB = sb, aLoB = sb + 2*SZA;
    const unsigned bHiB = sb + 4*SZA, bLoB = sb + 4*SZA + 2*SZB;

    const bf16* Ah = Ahi;
    const bf16* Al = Alo;
    const bf16* Bh = Bhi;
    const bf16* Bl = Blo;

    const int bm0 = blockIdx.y * BM, bn0 = blockIdx.x * BN;
    const int tid = threadIdx.x, lane = tid & 31, wid = tid >> 5;
    const int wm = (wid / WX) * WTM, wn = (wid % WX) * WTN;
    const int lr = lane & 15, h8 = lane >> 4;

    float acc[MF][NF][4];
    #pragma unroll
    for (int a = 0; a < MF; a++)
        #pragma unroll
        for (int b = 0; b < NF; b++)
            #pragma unroll
            for (int c = 0; c < 4; c++) acc[a][b][c] = 0.0f;

    auto loadTiles = [&](int k0, int buf) {
        #pragma unroll 2
        for (int t = tid; t < BM * 8; t += NT) {
            int r = t >> 3, c = t & 7;
            long go = (long)(bm0 + r) * lda + k0 + c * 8;
            unsigned so = (unsigned)(((r << 3) + (c ^ (r & 7))) << 4);
            cpa16(aHiB + buf * SZA + so, Ah + go);
            cpa16(aLoB + buf * SZA + so, Al + go);
        }
        #pragma unroll 2
        for (int t = tid; t < BN * 8; t += NT) {
            int r = t >> 3, c = t & 7;
            long go = (long)(bn0 + r) * ldb + k0 + c * 8;
            unsigned so = (unsigned)(((r << 3) + (c ^ (r & 7))) << 4);
            cpa16(bHiB + buf * SZB + so, Bh + go);
            cpa16(bLoB + buf * SZB + so, Bl + go);
        }
    };

    auto comp = [&](int buf) {
        const unsigned aH = aHiB + buf * SZA, aL = aLoB + buf * SZA;
        const unsigned bH = bHiB + buf * SZB, bL = bLoB + buf * SZB;
        #pragma unroll
        for (int ks = 0; ks < 4; ks++) {
            unsigned AH[MF][4], AL[MF][4], BH[NP][4], BL[NP][4];
            #pragma unroll
            for (int mf = 0; mf < MF; mf++) {
                int row = wm + mf * 16 + lr;
                unsigned off = (unsigned)(((row << 3) + ((ks*2 + h8) ^ (row & 7))) << 4);
                ldm4(AH[mf][0], AH[mf][1], AH[mf][2], AH[mf][3], aH + off);
                ldm4(AL[mf][0], AL[mf][1], AL[mf][2], AL[mf][3], aL + off);
            }
            #pragma unroll
            for (int p = 0; p < NP; p++) {
                int row = wn + p * 16 + lr;
                unsigned off = (unsigned)(((row << 3) + ((ks*2 + h8) ^ (row & 7))) << 4);
                ldm4(BH[p][0], BH[p][1], BH[p][2], BH[p][3], bH + off);
                ldm4(BL[p][0], BL[p][1], BL[p][2], BL[p][3], bL + off);
            }
            #pragma unroll
            for (int mf = 0; mf < MF; mf++)
                #pragma unroll
                for (int p = 0; p < NP; p++) {
                    mma16816(acc[mf][2*p],   AH[mf], BH[p][0], BH[p][2]);
                    mma16816(acc[mf][2*p],   AH[mf], BL[p][0], BL[p][2]);
                    mma16816(acc[mf][2*p],   AL[mf], BH[p][0], BH[p][2]);
                    mma16816(acc[mf][2*p+1], AH[mf], BH[p][1], BH[p][3]);
                    mma16816(acc[mf][2*p+1], AH[mf], BL[p][1], BL[p][3]);
                    mma16816(acc[mf][2*p+1], AL[mf], BH[p][1], BH[p][3]);
                }
        }
    };

    loadTiles(0, 0); cpcommit();
    const int nk = K >> 6;
    for (int kt = 0; kt < nk; kt++) {
        int buf = kt & 1;
        if (kt + 1 < nk) { loadTiles((kt + 1) << 6, buf ^ 1); cpcommit(); cpwait<1>(); }
        else             { cpwait<0>(); }
        __syncthreads();
        comp(buf);
        __syncthreads();
    }

    #pragma unroll
    for (int mf = 0; mf < MF; mf++)
        #pragma unroll
        for (int nf = 0; nf < NF; nf++)
            #pragma unroll
            for (int r = 0; r < 2; r++) {
                int m = bm0 + wm + mf * 16 + (lane >> 2) + r * 8;
                int n = bn0 + wn + nf * 8 + (lane & 3) * 2;
                float v0 = acc[mf][nf][r*2], v1 = acc[mf][nf][r*2+1];
                long o = (long)m * ldc + n;
                if constexpr (EPI == 0) {
                    float2 w; w.x = v0; w.y = v1;
                    *(float2*)&C[o] = w;
                } else if constexpr (EPI == 1) {
                    float2 w;
                    w.x = v0 + bias[n] + resid[(long)m * ldr + n];
                    w.y = v1 + bias[n+1] + resid[(long)m * ldr + n + 1];
                    *(float2*)&C[o] = w;
                } else {
                    v0 = gelu_f(v0 + bias[n]);
                    v1 = gelu_f(v1 + bias[n+1]);
                    bf16 h0,l0,h1,l1;
                    bsplit(v0,h0,l0); bsplit(v1,h1,l1);
                    *(bf162*)&Chi[o] = mk2(h0,h1);
                    *(bf162*)&Clo[o] = mk2(l0,l1);
                }
            }
}

// -------------------- host orchestration -----------------------------------
#define SMB(BM,BN) ((BM + BN) * 512)

extern "C" void kernel_launch(void* const* d_in, const int* in_sizes, int n_in,
                              void* d_out, int out_size) {
    (void)in_sizes; (void)n_in; (void)out_size;
    const float* x    = (const float*)d_in[0];
    const float* bias = (const float*)d_in[1];
    const float* wqkv = (const float*)d_in[2];
    const float* wout = (const float*)d_in[3];
    const float* bout = (const float*)d_in[4];
    const float* ln1g = (const float*)d_in[5];
    const float* ln1b = (const float*)d_in[6];
    const float* w1   = (const float*)d_in[7];
    const float* b1   = (const float*)d_in[8];
    const float* w2   = (const float*)d_in[9];
    const float* b2   = (const float*)d_in[10];
    const float* ln2g = (const float*)d_in[11];
    const float* ln2b = (const float*)d_in[12];
    const float* lnfg = (const float*)d_in[13];
    const float* lnfb = (const float*)d_in[14];

    float *px, *pqkv, *pqkvb;
    bf16 *phh, *phl, *pbh, *pbl, *pqh, *pql, *pkh, *pkl, *pvh, *pvl;
    bf16 *paoh, *paol, *pfh, *pfl;
    bf16 *pwqh, *pwql, *pwoh, *pwol, *pw1h, *pw1l, *pw2h, *pw2l;
    cudaGetSymbolAddress((void**)&px,    g_x);
    cudaGetSymbolAddress((void**)&pqkv,  g_qkv);
    cudaGetSymbolAddress((void**)&pqkvb, g_qkvb);
    cudaGetSymbolAddress((void**)&phh,   g_h_hi);    cudaGetSymbolAddress((void**)&phl, g_h_lo);
    cudaGetSymbolAddress((void**)&pbh,   g_bias_hi); cudaGetSymbolAddress((void**)&pbl, g_bias_lo);
    cudaGetSymbolAddress((void**)&pqh,   g_QQ_hi);   cudaGetSymbolAddress((void**)&pql, g_QQ_lo);
    cudaGetSymbolAddress((void**)&pkh,   g_KK_hi);   cudaGetSymbolAddress((void**)&pkl, g_KK_lo);
    cudaGetSymbolAddress((void**)&pvh,   g_VT_hi);   cudaGetSymbolAddress((void**)&pvl, g_VT_lo);
    cudaGetSymbolAddress((void**)&paoh,  g_ao_hi);   cudaGetSymbolAddress((void**)&paol, g_ao_lo);
    cudaGetSymbolAddress((void**)&pfh,   g_ff_hi);   cudaGetSymbolAddress((void**)&pfl, g_ff_lo);
    cudaGetSymbolAddress((void**)&pwqh,  g_wqkvT_hi); cudaGetSymbolAddress((void**)&pwql, g_wqkvT_lo);
    cudaGetSymbolAddress((void**)&pwoh,  g_woutT_hi); cudaGetSymbolAddress((void**)&pwol, g_woutT_lo);
    cudaGetSymbolAddress((void**)&pw1h,  g_w1T_hi);  cudaGetSymbolAddress((void**)&pw1l, g_w1T_lo);
    cudaGetSymbolAddress((void**)&pw2h,  g_w2T_hi);  cudaGetSymbolAddress((void**)&pw2l, g_w2T_lo);

    cudaFuncSetAttribute(bgemm<128,128,4,2,0>, cudaFuncAttributeMaxDynamicSharedMemorySize, SMB(128,128));
    cudaFuncSetAttribute(bgemm<128,128,4,2,1>, cudaFuncAttributeMaxDynamicSharedMemorySize, SMB(128,128));
    cudaFuncSetAttribute(bgemm<128,128,4,2,2>, cudaFuncAttributeMaxDynamicSharedMemorySize, SMB(128,128));
    cudaFuncSetAttribute(flash_k, cudaFuncAttributeMaxDynamicSharedMemorySize, FA_SMEM);

    const float scale = 0.125f;

    cudaMemcpyAsync(px, x, sizeof(float) * MTOK * DIMM, cudaMemcpyDeviceToDevice);

    // Ordered so a qkv bgemm lands at ncu's sampled launch index (skip 5).
    wconv<<<dim3(3072/32, 1024/32), 256>>>(wqkv, pwqh, pwql, 1024, 3072);
    ln_k<true><<<MTOK, 256>>>(px, ln1g, ln1b, nullptr, phh, phl);
    fconv<<<MTOK*DIMM/1024, 256>>>(bias, pbh, pbl);
    wconv<<<dim3(1024/32, 1024/32), 256>>>(wout, pwoh, pwol, 1024, 1024);
    bgemm<128,128,4,2,0><<<dim3(24, 32), 256, SMB(128,128)>>>(
        phh, phl, pwqh, pwql, pqkv, nullptr, nullptr,
        1024, 1024, 3072, 1024, nullptr, nullptr, 0);
    bgemm<128,128,4,2,0><<<dim3(16, 32), 256, SMB(128,128)>>>(
        pbh, pbl, pwqh, pwql, pqkvb, nullptr, nullptr,
        1024, 1024, 2048, 1024, nullptr, nullptr, 0);

    // remaining one-time weight conversions
    wconv<<<dim3(4096/32, 1024/32), 256>>>(w1, pw1h, pw1l, 1024, 4096);
    wconv<<<dim3(1024/32, 4096/32), 256>>>(w2, pw2h, pw2l, 4096, 1024);
    for (int l = 1; l < DEPTH; l++) {
        wconv<<<dim3(3072/32, 1024/32), 256>>>(wqkv + (long)l*1024*3072, pwqh + (long)l*3072*1024, pwql + (long)l*3072*1024, 1024, 3072);
        wconv<<<dim3(1024/32, 1024/32), 256>>>(wout + (long)l*1024*1024, pwoh + (long)l*1024*1024, pwol + (long)l*1024*1024, 1024, 1024);
        wconv<<<dim3(4096/32, 1024/32), 256>>>(w1   + (long)l*1024*4096, pw1h + (long)l*4096*1024, pw1l + (long)l*4096*1024, 1024, 4096);
        wconv<<<dim3(1024/32, 4096/32), 256>>>(w2   + (long)l*4096*1024, pw2h + (long)l*1024*4096, pw2l + (long)l*1024*4096, 4096, 1024);
    }

    for (int l = 0; l < DEPTH; l++) {
        bf16 *wqh = pwqh + (long)l*3072*1024, *wql = pwql + (long)l*3072*1024;
        bf16 *woh = pwoh + (long)l*1024*1024, *wol = pwol + (long)l*1024*1024;
        bf16 *w1h = pw1h + (long)l*4096*1024, *w1l = pw1l + (long)l*4096*1024;
        bf16 *w2h = pw2h + (long)l*1024*4096, *w2l = pw2l + (long)l*1024*4096;

        if (l > 0) {
            // LN1 -> bf16 h, then qkv + qkvb projections (layer 0 done above)
            ln_k<true><<<MTOK, 256>>>(px, ln1g + l*DIMM, ln1b + l*DIMM, nullptr, phh, phl);
            bgemm<128,128,4,2,0><<<dim3(24, 32), 256, SMB(128,128)>>>(
                phh, phl, wqh, wql, pqkv, nullptr, nullptr,
                1024, 1024, 3072, 1024, nullptr, nullptr, 0);
            bgemm<128,128,4,2,0><<<dim3(16, 32), 256, SMB(128,128)>>>(
                pbh, pbl, wqh, wql, pqkvb, nullptr, nullptr,
                1024, 1024, 2048, 1024, nullptr, nullptr, 0);
        }

        pack_qk<<<(NBH*TT*128)/256, 256>>>(pqkv, pqkvb, pqh, pql, pkh, pkl, scale);
        vconv<<<dim3(32, 2, NBH), 256>>>(pqkv, pvh, pvl);

        // fused attention -> ao (bf16 hi/lo, token-major)
        flash_k<<<dim3(8, NBH), 256, FA_SMEM>>>(
            pqh, pql, pkh, pkl, pvh, pvl, paoh, paol);

        // x = x + ao @ Wout + bout
        bgemm<128,128,4,2,1><<<dim3(8, 32), 256, SMB(128,128)>>>(
            paoh, paol, woh, wol, px, nullptr, nullptr,
            1024, 1024, 1024, 1024, bout + l*DIMM, px, 1024);

        // LN2 -> bf16 h
        ln_k<true><<<MTOK, 256>>>(px, ln2g + l*DIMM, ln2b + l*DIMM, nullptr, phh, phl);

        // ff = gelu(h @ W1 + b1) -> bf16
        bgemm<128,128,4,2,2><<<dim3(32, 32), 256, SMB(128,128)>>>(
            phh, phl, w1h, w1l, nullptr, pfh, pfl,
            1024, 1024, 4096, 1024, b1 + l*FFI, nullptr, 0);

        // x = x + ff @ W2 + b2
        bgemm<128,128,4,2,1><<<dim3(8, 32), 256, SMB(128,128)>>>(
            pfh, pfl, w2h, w2l, px, nullptr, nullptr,
            4096, 4096, 1024, 4096, b2 + l*DIMM, px, 1024);
    }

    // final LN -> fp32 out
    ln_k<false><<<MTOK, 256>>>(px, lnfg, lnfb, (float*)d_out, nullptr, nullptr);
}

// round 8
// speedup vs baseline: 2.5914x; 1.0239x over previous
#include <cuda_runtime.h>
#include <cuda_bf16.h>
#include <math.h>

// ---------------------------------------------------------------------------
// TemporalTransformer forward. Dense GEMMs: bf16x3 split on mma.sync tensor
// cores, BK=32 / 3-stage cp.async pipeline / 2 CTAs per SM.
// Attention: fused flash kernel (QK^T + online softmax + PV).
// NOTE: harness compiles for sm_100 (no 'a') -> tcgen05 unavailable.
// ---------------------------------------------------------------------------

#define DIMM   1024
#define DEPTH  4
#define HEADS  16
#define INNER  1024
#define FFI    4096
#define BB     4
#define TT     1024
#define MTOK   (BB*TT)
#define NBH    (BB*HEADS)

typedef __nv_bfloat16 bf16;
typedef __nv_bfloat162 bf162;

// -------------------- device-global scratch --------------------------------
__device__ float g_x   [MTOK*DIMM];
__device__ float g_qkv [MTOK*3*INNER];
__device__ float g_qkvb[MTOK*2*INNER];

__device__ bf16 g_h_hi [MTOK*DIMM],      g_h_lo [MTOK*DIMM];
__device__ bf16 g_bias_hi[MTOK*DIMM],    g_bias_lo[MTOK*DIMM];
__device__ bf16 g_QQ_hi[NBH*TT*128],     g_QQ_lo[NBH*TT*128];
__device__ bf16 g_KK_hi[NBH*TT*128],     g_KK_lo[NBH*TT*128];
__device__ bf16 g_VT_hi[NBH*64*TT],      g_VT_lo[NBH*64*TT];
__device__ bf16 g_ao_hi[MTOK*INNER],     g_ao_lo[MTOK*INNER];
__device__ bf16 g_ff_hi[(long)MTOK*FFI], g_ff_lo[(long)MTOK*FFI];
__device__ bf16 g_wqkvT_hi[DEPTH*3072*1024], g_wqkvT_lo[DEPTH*3072*1024];
__device__ bf16 g_woutT_hi[DEPTH*1024*1024], g_woutT_lo[DEPTH*1024*1024];
__device__ bf16 g_w1T_hi [DEPTH*4096*1024], g_w1T_lo [DEPTH*4096*1024];
__device__ bf16 g_w2T_hi [DEPTH*1024*4096], g_w2T_lo [DEPTH*1024*4096];

// -------------------- helpers ----------------------------------------------
__device__ __forceinline__ bf162 mk2(bf16 a, bf16 b) {
    bf162 t; t.x = a; t.y = b; return t;
}

__device__ __forceinline__ void bsplit(float v, bf16& h, bf16& l) {
    bf16 hb = __float2bfloat16_rz(v);
    h = hb;
    l = __float2bfloat16(v - __bfloat162float(hb));
}

__device__ __forceinline__ unsigned pk2(bf16 a, bf16 b) {
    bf162 t; t.x = a; t.y = b;
    return *(unsigned*)&t;
}

__device__ __forceinline__ float gelu_f(float x) {
    return 0.5f * x * (1.0f + erff(x * 0.70710678118654752440f));
}

__device__ __forceinline__ void ldm4(unsigned& r0, unsigned& r1, unsigned& r2,
                                     unsigned& r3, unsigned a) {
    asm volatile("ldmatrix.sync.aligned.m8n8.x4.shared.b16 {%0,%1,%2,%3}, [%4];"
                 : "=r"(r0), "=r"(r1), "=r"(r2), "=r"(r3) : "r"(a));
}

__device__ __forceinline__ void mma16816(float* d, const unsigned* a,
                                         unsigned b0, unsigned b1) {
    asm volatile(
        "mma.sync.aligned.m16n8k16.row.col.f32.bf16.bf16.f32 "
        "{%0,%1,%2,%3}, {%4,%5,%6,%7}, {%8,%9}, {%0,%1,%2,%3};"
        : "+f"(d[0]), "+f"(d[1]), "+f"(d[2]), "+f"(d[3])
        : "r"(a[0]), "r"(a[1]), "r"(a[2]), "r"(a[3]), "r"(b0), "r"(b1));
}

__device__ __forceinline__ void cpa16(unsigned dst, const void* src) {
    asm volatile("cp.async.cg.shared.global [%0], [%1], 16;" :: "r"(dst), "l"(src));
}
__device__ __forceinline__ void cpcommit() { asm volatile("cp.async.commit_group;"); }
template<int N> __device__ __forceinline__ void cpwait() {
    asm volatile("cp.async.wait_group %0;" :: "n"(N));
}

// -------------------- block reductions (256 threads) -----------------------
__device__ __forceinline__ float blk_sum(float v) {
    __shared__ float sh[32];
    int lane = threadIdx.x & 31, w = threadIdx.x >> 5;
    #pragma unroll
    for (int o = 16; o; o >>= 1) v += __shfl_xor_sync(0xffffffffu, v, o);
    if (lane == 0) sh[w] = v;
    __syncthreads();
    if (w == 0) {
        v = (lane < 8) ? sh[lane] : 0.0f;
        #pragma unroll
        for (int o = 4; o; o >>= 1) v += __shfl_xor_sync(0xffffffffu, v, o);
        if (lane == 0) sh[0] = v;
    }
    __syncthreads();
    v = sh[0];
    __syncthreads();
    return v;
}

// -------------------- LayerNorm --------------------------------------------
template<bool BFOUT>
__global__ void ln_k(const float* __restrict__ x, const float* __restrict__ g,
                     const float* __restrict__ b, float* __restrict__ of,
                     bf16* __restrict__ ohi, bf16* __restrict__ olo) {
    long row = blockIdx.x;
    float4 v = ((const float4*)(x + row * DIMM))[threadIdx.x];
    float mu = blk_sum(v.x + v.y + v.z + v.w) * (1.0f / DIMM);
    float dx = v.x - mu, dy = v.y - mu, dz = v.z - mu, dw = v.w - mu;
    float var = blk_sum(dx*dx + dy*dy + dz*dz + dw*dw) * (1.0f / DIMM);
    float inv = rsqrtf(var + 1e-5f);
    float4 gg = ((const float4*)g)[threadIdx.x];
    float4 bb = ((const float4*)b)[threadIdx.x];
    float r0 = dx*inv*gg.x + bb.x, r1 = dy*inv*gg.y + bb.y;
    float r2 = dz*inv*gg.z + bb.z, r3 = dw*inv*gg.w + bb.w;
    if (BFOUT) {
        bf16 h0,l0,h1,l1,h2,l2,h3,l3;
        bsplit(r0,h0,l0); bsplit(r1,h1,l1); bsplit(r2,h2,l2); bsplit(r3,h3,l3);
        ((bf162*)(ohi + row*DIMM))[threadIdx.x*2]   = mk2(h0,h1);
        ((bf162*)(ohi + row*DIMM))[threadIdx.x*2+1] = mk2(h2,h3);
        ((bf162*)(olo + row*DIMM))[threadIdx.x*2]   = mk2(l0,l1);
        ((bf162*)(olo + row*DIMM))[threadIdx.x*2+1] = mk2(l2,l3);
    } else {
        float4 r; r.x=r0; r.y=r1; r.z=r2; r.w=r3;
        ((float4*)(of + row*DIMM))[threadIdx.x] = r;
    }
}

// -------------------- weight transpose+split: W[K][N] -> [N][K] hi/lo ------
__global__ void wconv(const float* __restrict__ W, bf16* __restrict__ hi,
                      bf16* __restrict__ lo, int K, int N) {
    __shared__ float t[32][33];
    int k0 = blockIdx.y * 32, n0 = blockIdx.x * 32;
    int tx = threadIdx.x & 31, ty = threadIdx.x >> 5;
    #pragma unroll
    for (int r = 0; r < 4; r++)
        t[ty + r*8][tx] = W[(long)(k0 + ty + r*8) * N + n0 + tx];
    __syncthreads();
    #pragma unroll
    for (int r = 0; r < 4; r++) {
        float v = t[tx][ty + r*8];
        long o = (long)(n0 + ty + r*8) * K + k0 + tx;
        bf16 h, l; bsplit(v, h, l);
        hi[o] = h; lo[o] = l;
    }
}

// -------------------- elementwise fp32 -> bf16 hi/lo -----------------------
__global__ void fconv(const float* __restrict__ s, bf16* __restrict__ hi,
                      bf16* __restrict__ lo) {
    long i = (long)blockIdx.x * blockDim.x + threadIdx.x;
    float4 v = ((const float4*)s)[i];
    bf16 h0,l0,h1,l1,h2,l2,h3,l3;
    bsplit(v.x,h0,l0); bsplit(v.y,h1,l1); bsplit(v.z,h2,l2); bsplit(v.w,h3,l3);
    ((bf162*)hi)[i*2]   = mk2(h0,h1);
    ((bf162*)hi)[i*2+1] = mk2(h2,h3);
    ((bf162*)lo)[i*2]   = mk2(l0,l1);
    ((bf162*)lo)[i*2+1] = mk2(l2,l3);
}

// -------------------- pack scale*[q|qb], [k|kb] per head -------------------
__global__ void pack_qk(const float* __restrict__ qkv, const float* __restrict__ qkvb,
                        bf16* __restrict__ qhi, bf16* __restrict__ qlo,
                        bf16* __restrict__ khi, bf16* __restrict__ klo, float scale) {
    int idx = blockIdx.x * blockDim.x + threadIdx.x;   // NBH*TT*128
    int d  = idx & 127;
    int i  = (idx >> 7) & (TT - 1);
    int bh = idx >> 17;
    int b = bh >> 4, h = bh & 15;
    long tok = (long)b * TT + i;
    float q, k;
    if (d < 64) {
        q = qkv[tok * 3072 + h * 64 + d];
        k = qkv[tok * 3072 + INNER + h * 64 + d];
    } else {
        q = qkvb[tok * 2048 + h * 64 + (d - 64)];
        k = qkvb[tok * 2048 + INNER + h * 64 + (d - 64)];
    }
    bf16 hh, ll;
    bsplit(q * scale, hh, ll);  qhi[idx] = hh; qlo[idx] = ll;
    bsplit(k, hh, ll);          khi[idx] = hh; klo[idx] = ll;
}

// -------------------- V transpose: qkv V part -> [bh][d][t] hi/lo ----------
__global__ void vconv(const float* __restrict__ qkv, bf16* __restrict__ vhi,
                      bf16* __restrict__ vlo) {
    __shared__ float t[32][33];
    int i0 = blockIdx.x * 32, d0 = blockIdx.y * 32, bh = blockIdx.z;
    int b = bh >> 4, h = bh & 15;
    int tx = threadIdx.x & 31, ty = threadIdx.x >> 5;
    #pragma unroll
    for (int r = 0; r < 4; r++)
        t[ty + r*8][tx] = qkv[(long)(b*TT + i0 + ty + r*8) * 3072 + 2048 + h*64 + d0 + tx];
    __syncthreads();
    #pragma unroll
    for (int r = 0; r < 4; r++) {
        float v = t[tx][ty + r*8];
        long o = (long)(bh*64 + d0 + ty + r*8) * TT + i0 + tx;
        bf16 hh, ll; bsplit(v, hh, ll);
        vhi[o] = hh; vlo[o] = ll;
    }
}

// -------------------- bf16x3 GEMM, BK=32, 3-stage, 2 CTAs/SM ----------------
// C[m,n] = sum_k A[m,k]*B[n,k]; A/B as (hi,lo) bf16 pairs, [row][k].
// smem stage (32 KB): A_hi 8K | A_lo 8K | B_hi 8K | B_lo 8K.
// Packed layout: 2 logical rows per 128B smem row; for (row r, 16B chunk c):
//   off = (r>>1)*128 + ((((r&1)*4 + c) ^ ((r>>1)&7)) << 4)   (conflict-free)
// EPI: 0 plain fp32; 1 fp32 + bias[n] + resid; 2 gelu(+bias)->bf16 pair.
#define BG_SMEM (3*32768)

__device__ __forceinline__ unsigned bg_off(int r, int c) {
    return (unsigned)(((r >> 1) << 7) + (((((r & 1) << 2) + c) ^ ((r >> 1) & 7)) << 4));
}

template<int EPI>
__global__ void __launch_bounds__(256, 2) bgemm(
    const bf16* __restrict__ Ahi, const bf16* __restrict__ Alo,
    const bf16* __restrict__ Bhi, const bf16* __restrict__ Blo,
    float* __restrict__ C, bf16* __restrict__ Chi, bf16* __restrict__ Clo,
    int lda, int ldb, int ldc, int K,
    const float* __restrict__ bias, const float* __restrict__ resid, int ldr)
{
    extern __shared__ __align__(128) char dsm[];
    const unsigned sb = (unsigned)__cvta_generic_to_shared(dsm);

    const int bm0 = blockIdx.y * 128, bn0 = blockIdx.x * 128;
    const int tid = threadIdx.x, lane = tid & 31, wid = tid >> 5;
    // 8 warps: WX=4 x WY=2; warp tile 64x32
    const int wm = (wid >> 2) * 64, wn = (wid & 3) * 32;
    const int lr = lane & 15, h8 = lane >> 4;

    float acc[4][4][4];
    #pragma unroll
    for (int a = 0; a < 4; a++)
        #pragma unroll
        for (int b = 0; b < 4; b++)
            #pragma unroll
            for (int c = 0; c < 4; c++) acc[a][b][c] = 0.0f;

    auto loadStage = [&](int ch, int s) {
        unsigned base = sb + s * 32768;
        int k0 = ch << 5;
        #pragma unroll
        for (int i = 0; i < 2; i++) {
            int t = i * 256 + tid;          // t < 512
            int r = t >> 2, c = t & 3;
            unsigned so = bg_off(r, c);
            long goA = (long)(bm0 + r) * lda + k0 + c * 8;
            long goB = (long)(bn0 + r) * ldb + k0 + c * 8;
            cpa16(base + so,         Ahi + goA);
            cpa16(base + 8192 + so,  Alo + goA);
            cpa16(base + 16384 + so, Bhi + goB);
            cpa16(base + 24576 + so, Blo + goB);
        }
    };

    auto comp = [&](int s) {
        unsigned aH = sb + s * 32768;
        unsigned aL = aH + 8192, bH = aH + 16384, bL = aH + 24576;
        #pragma unroll
        for (int ks = 0; ks < 2; ks++) {
            int cc = ks * 2 + h8;
            unsigned AH[4][4], AL[4][4];
            #pragma unroll
            for (int mf = 0; mf < 4; mf++) {
                unsigned off = bg_off(wm + mf * 16 + lr, cc);
                ldm4(AH[mf][0], AH[mf][1], AH[mf][2], AH[mf][3], aH + off);
                ldm4(AL[mf][0], AL[mf][1], AL[mf][2], AL[mf][3], aL + off);
            }
            #pragma unroll
            for (int p = 0; p < 2; p++) {
                unsigned off = bg_off(wn + p * 16 + lr, cc);
                unsigned BH[4], BL[4];
                ldm4(BH[0], BH[1], BH[2], BH[3], bH + off);
                ldm4(BL[0], BL[1], BL[2], BL[3], bL + off);
                #pragma unroll
                for (int mf = 0; mf < 4; mf++) {
                    mma16816(acc[mf][2*p],   AH[mf], BH[0], BH[2]);
                    mma16816(acc[mf][2*p],   AH[mf], BL[0], BL[2]);
                    mma16816(acc[mf][2*p],   AL[mf], BH[0], BH[2]);
                    mma16816(acc[mf][2*p+1], AH[mf], BH[1], BH[3]);
                    mma16816(acc[mf][2*p+1], AH[mf], BL[1], BL[3]);
                    mma16816(acc[mf][2*p+1], AL[mf], BH[1], BH[3]);
                }
            }
        }
    };

    const int nch = K >> 5;
    loadStage(0, 0); cpcommit();
    loadStage(1, 1); cpcommit();
    int slot = 0;
    for (int ch = 0; ch < nch; ch++) {
        if (ch + 1 < nch) { cpwait<1>(); } else { cpwait<0>(); }
        __syncthreads();
        if (ch + 2 < nch) {
            int ns = slot + 2; if (ns >= 3) ns -= 3;
            loadStage(ch + 2, ns); cpcommit();
        }
        comp(slot);
        if (++slot == 3) slot = 0;
    }

    // epilogue
    #pragma unroll
    for (int mf = 0; mf < 4; mf++)
        #pragma unroll
        for (int nf = 0; nf < 4; nf++)
            #pragma unroll
            for (int r = 0; r < 2; r++) {
                int m = bm0 + wm + mf * 16 + (lane >> 2) + r * 8;
                int n = bn0 + wn + nf * 8 + (lane & 3) * 2;
                float v0 = acc[mf][nf][r*2], v1 = acc[mf][nf][r*2+1];
                long o = (long)m * ldc + n;
                if constexpr (EPI == 0) {
                    float2 w; w.x = v0; w.y = v1;
                    *(float2*)&C[o] = w;
                } else if constexpr (EPI == 1) {
                    float2 w;
                    w.x = v0 + bias[n] + resid[(long)m * ldr + n];
                    w.y = v1 + bias[n+1] + resid[(long)m * ldr + n + 1];
                    *(float2*)&C[o] = w;
                } else {
                    v0 = gelu_f(v0 + bias[n]);
                    v1 = gelu_f(v1 + bias[n+1]);
                    bf16 h0,l0,h1,l1;
                    bsplit(v0,h0,l0); bsplit(v1,h1,l1);
                    *(bf162*)&Chi[o] = mk2(h0,h1);
                    *(bf162*)&Clo[o] = mk2(l0,l1);
                }
            }
}

// -------------------- fused flash attention --------------------------------
#define FA_SQH 0
#define FA_SQL 32768
#define FA_SKH 65536
#define FA_SKL 98304
#define FA_SVH 131072
#define FA_SVL 147456
#define FA_SMEM 163840

__global__ void __launch_bounds__(256) flash_k(
    const bf16* __restrict__ Qh, const bf16* __restrict__ Ql,
    const bf16* __restrict__ Kh, const bf16* __restrict__ Kl,
    const bf16* __restrict__ Vh, const bf16* __restrict__ Vl,
    bf16* __restrict__ Ohi, bf16* __restrict__ Olo)
{
    extern __shared__ __align__(128) char fsm[];
    const unsigned sb = (unsigned)__cvta_generic_to_shared(fsm);

    const int mt = blockIdx.x, bh = blockIdx.y;
    const int m0 = mt * 128;
    const int tid = threadIdx.x, lane = tid & 31, wid = tid >> 5;
    const int wm = wid * 16;
    const int lr = lane & 15, h8 = lane >> 4;

    const bf16* Qhp = Qh + ((long)bh * TT + m0) * 128;
    const bf16* Qlp = Ql + ((long)bh * TT + m0) * 128;
    const bf16* Khp = Kh + (long)bh * TT * 128;
    const bf16* Klp = Kl + (long)bh * TT * 128;
    const bf16* Vhp = Vh + (long)bh * 64 * TT;
    const bf16* Vlp = Vl + (long)bh * 64 * TT;

    #pragma unroll 4
    for (int t = tid; t < 2048; t += 256) {
        int r = t >> 4, c = t & 15;
        long go = (long)r * 128 + c * 8;
        unsigned so = (unsigned)(((r << 4) + (c ^ (r & 7))) << 4);
        cpa16(sb + FA_SQH + so, Qhp + go);
        cpa16(sb + FA_SQL + so, Qlp + go);
    }
    cpcommit();

    float oacc[8][4];
    #pragma unroll
    for (int i = 0; i < 8; i++)
        #pragma unroll
        for (int j = 0; j < 4; j++) oacc[i][j] = 0.0f;
    float mrow0 = -INFINITY, mrow1 = -INFINITY;
    float lrow0 = 0.0f, lrow1 = 0.0f;

    for (int jt = 0; jt < 8; jt++) {
        #pragma unroll 4
        for (int t = tid; t < 2048; t += 256) {
            int r = t >> 4, c = t & 15;
            long go = (long)(jt * 128 + r) * 128 + c * 8;
            unsigned so = (unsigned)(((r << 4) + (c ^ (r & 7))) << 4);
            cpa16(sb + FA_SKH + so, Khp + go);
            cpa16(sb + FA_SKL + so, Klp + go);
        }
        #pragma unroll 2
        for (int t = tid; t < 1024; t += 256) {
            int r = t >> 4, c = t & 15;
            long go = (long)r * TT + jt * 128 + c * 8;
            unsigned so = (unsigned)(((r << 4) + (c ^ (r & 7))) << 4);
            cpa16(sb + FA_SVH + so, Vhp + go);
            cpa16(sb + FA_SVL + so, Vlp + go);
        }
        cpcommit();
        cpwait<0>();
        __syncthreads();

        float sacc[16][4];
        #pragma unroll
        for (int i = 0; i < 16; i++)
            #pragma unroll
            for (int j = 0; j < 4; j++) sacc[i][j] = 0.0f;

        #pragma unroll
        for (int ks = 0; ks < 8; ks++) {
            int c = ks * 2 + h8;
            unsigned AH[4], AL[4];
            {
                int row = wm + lr;
                unsigned off = (unsigned)(((row << 4) + (c ^ (row & 7))) << 4);
                ldm4(AH[0], AH[1], AH[2], AH[3], sb + FA_SQH + off);
                ldm4(AL[0], AL[1], AL[2], AL[3], sb + FA_SQL + off);
            }
            #pragma unroll
            for (int p = 0; p < 8; p++) {
                int row = p * 16 + lr;
                unsigned off = (unsigned)(((row << 4) + (c ^ (row & 7))) << 4);
                unsigned BH[4], BL[4];
                ldm4(BH[0], BH[1], BH[2], BH[3], sb + FA_SKH + off);
                ldm4(BL[0], BL[1], BL[2], BL[3], sb + FA_SKL + off);
                mma16816(sacc[2*p],   AH, BH[0], BH[2]);
                mma16816(sacc[2*p],   AH, BL[0], BL[2]);
                mma16816(sacc[2*p],   AL, BH[0], BH[2]);
                mma16816(sacc[2*p+1], AH, BH[1], BH[3]);
                mma16816(sacc[2*p+1], AH, BL[1], BL[3]);
                mma16816(sacc[2*p+1], AL, BH[1], BH[3]);
            }
        }

        float tm0 = -INFINITY, tm1 = -INFINITY;
        #pragma unroll
        for (int nf = 0; nf < 16; nf++) {
            tm0 = fmaxf(tm0, fmaxf(sacc[nf][0], sacc[nf][1]));
            tm1 = fmaxf(tm1, fmaxf(sacc[nf][2], sacc[nf][3]));
        }
        tm0 = fmaxf(tm0, __shfl_xor_sync(0xffffffffu, tm0, 1));
        tm0 = fmaxf(tm0, __shfl_xor_sync(0xffffffffu, tm0, 2));
        tm1 = fmaxf(tm1, __shfl_xor_sync(0xffffffffu, tm1, 1));
        tm1 = fmaxf(tm1, __shfl_xor_sync(0xffffffffu, tm1, 2));
        float mn0 = fmaxf(mrow0, tm0), mn1 = fmaxf(mrow1, tm1);
        float cor0 = __expf(mrow0 - mn0), cor1 = __expf(mrow1 - mn1);
        mrow0 = mn0; mrow1 = mn1;
        #pragma unroll
        for (int nf = 0; nf < 8; nf++) {
            oacc[nf][0] *= cor0; oacc[nf][1] *= cor0;
            oacc[nf][2] *= cor1; oacc[nf][3] *= cor1;
        }

        float rs0 = 0.0f, rs1 = 0.0f;
        #pragma unroll
        for (int ks = 0; ks < 8; ks++) {
            float p00 = __expf(sacc[2*ks][0]   - mn0);
            float p01 = __expf(sacc[2*ks][1]   - mn0);
            float p02 = __expf(sacc[2*ks][2]   - mn1);
            float p03 = __expf(sacc[2*ks][3]   - mn1);
            float p10 = __expf(sacc[2*ks+1][0] - mn0);
            float p11 = __expf(sacc[2*ks+1][1] - mn0);
            float p12 = __expf(sacc[2*ks+1][2] - mn1);
            float p13 = __expf(sacc[2*ks+1][3] - mn1);
            rs0 += p00 + p01 + p10 + p11;
            rs1 += p02 + p03 + p12 + p13;
            bf16 h, l, h2, l2;
            unsigned PH[4], PL[4];
            bsplit(p00, h, l); bsplit(p01, h2, l2);
            PH[0] = pk2(h, h2); PL[0] = pk2(l, l2);
            bsplit(p02, h, l); bsplit(p03, h2, l2);
            PH[1] = pk2(h, h2); PL[1] = pk2(l, l2);
            bsplit(p10, h, l); bsplit(p11, h2, l2);
            PH[2] = pk2(h, h2); PL[2] = pk2(l, l2);
            bsplit(p12, h, l); bsplit(p13, h2, l2);
            PH[3] = pk2(h, h2); PL[3] = pk2(l, l2);

            int c = ks * 2 + h8;
            #pragma unroll
            for (int p = 0; p < 4; p++) {
                int row = p * 16 + lr;
                unsigned off = (unsigned)(((row << 4) + (c ^ (row & 7))) << 4);
                unsigned BH[4], BL[4];
                ldm4(BH[0], BH[1], BH[2], BH[3], sb + FA_SVH + off);
                ldm4(BL[0], BL[1], BL[2], BL[3], sb + FA_SVL + off);
                mma16816(oacc[2*p],   PH, BH[0], BH[2]);
                mma16816(oacc[2*p],   PH, BL[0], BL[2]);
                mma16816(oacc[2*p],   PL, BH[0], BH[2]);
                mma16816(oacc[2*p+1], PH, BH[1], BH[3]);
                mma16816(oacc[2*p+1], PH, BL[1], BL[3]);
                mma16816(oacc[2*p+1], PL, BH[1], BH[3]);
            }
        }
        rs0 += __shfl_xor_sync(0xffffffffu, rs0, 1);
        rs0 += __shfl_xor_sync(0xffffffffu, rs0, 2);
        rs1 += __shfl_xor_sync(0xffffffffu, rs1, 1);
        rs1 += __shfl_xor_sync(0xffffffffu, rs1, 2);
        lrow0 = lrow0 * cor0 + rs0;
        lrow1 = lrow1 * cor1 + rs1;

        __syncthreads();
    }

    float inv0 = 1.0f / lrow0, inv1 = 1.0f / lrow1;
    int b = bh >> 4, h = bh & 15;
    int r0 = m0 + wm + (lane >> 2);
    int cb = h * 64 + (lane & 3) * 2;
    bf16* oh0 = Ohi + ((long)(b * TT + r0)) * INNER + cb;
    bf16* ol0 = Olo + ((long)(b * TT + r0)) * INNER + cb;
    bf16* oh1 = oh0 + 8L * INNER;
    bf16* ol1 = ol0 + 8L * INNER;
    #pragma unroll
    for (int nf = 0; nf < 8; nf++) {
        bf16 ha, la, hb2, lb2;
        bsplit(oacc[nf][0] * inv0, ha, la);
        bsplit(oacc[nf][1] * inv0, hb2, lb2);
        *(bf162*)(oh0 + nf * 8) = mk2(ha, hb2);
        *(bf162*)(ol0 + nf * 8) = mk2(la, lb2);
        bsplit(oacc[nf][2] * inv1, ha, la);
        bsplit(oacc[nf][3] * inv1, hb2, lb2);
        *(bf162*)(oh1 + nf * 8) = mk2(ha, hb2);
        *(bf162*)(ol1 + nf * 8) = mk2(la, lb2);
    }
}

// -------------------- host orchestration -----------------------------------
extern "C" void kernel_launch(void* const* d_in, const int* in_sizes, int n_in,
                              void* d_out, int out_size) {
    (void)in_sizes; (void)n_in; (void)out_size;
    const float* x    = (const float*)d_in[0];
    const float* bias = (const float*)d_in[1];
    const float* wqkv = (const float*)d_in[2];
    const float* wout = (const float*)d_in[3];
    const float* bout = (const float*)d_in[4];
    const float* ln1g = (const float*)d_in[5];
    const float* ln1b = (const float*)d_in[6];
    const float* w1   = (const float*)d_in[7];
    const float* b1   = (const float*)d_in[8];
    const float* w2   = (const float*)d_in[9];
    const float* b2   = (const float*)d_in[10];
    const float* ln2g = (const float*)d_in[11];
    const float* ln2b = (const float*)d_in[12];
    const float* lnfg = (const float*)d_in[13];
    const float* lnfb = (const float*)d_in[14];

    float *px, *pqkv, *pqkvb;
    bf16 *phh, *phl, *pbh, *pbl, *pqh, *pql, *pkh, *pkl, *pvh, *pvl;
    bf16 *paoh, *paol, *pfh, *pfl;
    bf16 *pwqh, *pwql, *pwoh, *pwol, *pw1h, *pw1l, *pw2h, *pw2l;
    cudaGetSymbolAddress((void**)&px,    g_x);
    cudaGetSymbolAddress((void**)&pqkv,  g_qkv);
    cudaGetSymbolAddress((void**)&pqkvb, g_qkvb);
    cudaGetSymbolAddress((void**)&phh,   g_h_hi);    cudaGetSymbolAddress((void**)&phl, g_h_lo);
    cudaGetSymbolAddress((void**)&pbh,   g_bias_hi); cudaGetSymbolAddress((void**)&pbl, g_bias_lo);
    cudaGetSymbolAddress((void**)&pqh,   g_QQ_hi);   cudaGetSymbolAddress((void**)&pql, g_QQ_lo);
    cudaGetSymbolAddress((void**)&pkh,   g_KK_hi);   cudaGetSymbolAddress((void**)&pkl, g_KK_lo);
    cudaGetSymbolAddress((void**)&pvh,   g_VT_hi);   cudaGetSymbolAddress((void**)&pvl, g_VT_lo);
    cudaGetSymbolAddress((void**)&paoh,  g_ao_hi);   cudaGetSymbolAddress((void**)&paol, g_ao_lo);
    cudaGetSymbolAddress((void**)&pfh,   g_ff_hi);   cudaGetSymbolAddress((void**)&pfl, g_ff_lo);
    cudaGetSymbolAddress((void**)&pwqh,  g_wqkvT_hi); cudaGetSymbolAddress((void**)&pwql, g_wqkvT_lo);
    cudaGetSymbolAddress((void**)&pwoh,  g_woutT_hi); cudaGetSymbolAddress((void**)&pwol, g_woutT_lo);
    cudaGetSymbolAddress((void**)&pw1h,  g_w1T_hi);  cudaGetSymbolAddress((void**)&pw1l, g_w1T_lo);
    cudaGetSymbolAddress((void**)&pw2h,  g_w2T_hi);  cudaGetSymbolAddress((void**)&pw2l, g_w2T_lo);

    cudaFuncSetAttribute(bgemm<0>, cudaFuncAttributeMaxDynamicSharedMemorySize, BG_SMEM);
    cudaFuncSetAttribute(bgemm<1>, cudaFuncAttributeMaxDynamicSharedMemorySize, BG_SMEM);
    cudaFuncSetAttribute(bgemm<2>, cudaFuncAttributeMaxDynamicSharedMemorySize, BG_SMEM);
    cudaFuncSetAttribute(flash_k, cudaFuncAttributeMaxDynamicSharedMemorySize, FA_SMEM);

    const float scale = 0.125f;

    cudaMemcpyAsync(px, x, sizeof(float) * MTOK * DIMM, cudaMemcpyDeviceToDevice);

    // 5 kernels precede the qkv bgemm so ncu (-s 5 -c 1) samples it.
    wconv<<<dim3(3072/32, 1024/32), 256>>>(wqkv, pwqh, pwql, 1024, 3072);
    ln_k<true><<<MTOK, 256>>>(px, ln1g, ln1b, nullptr, phh, phl);
    fconv<<<MTOK*DIMM/1024, 256>>>(bias, pbh, pbl);
    wconv<<<dim3(1024/32, 1024/32), 256>>>(wout, pwoh, pwol, 1024, 1024);
    wconv<<<dim3(4096/32, 1024/32), 256>>>(w1, pw1h, pw1l, 1024, 4096);
    bgemm<0><<<dim3(24, 32), 256, BG_SMEM>>>(
        phh, phl, pwqh, pwql, pqkv, nullptr, nullptr,
        1024, 1024, 3072, 1024, nullptr, nullptr, 0);
    bgemm<0><<<dim3(16, 32), 256, BG_SMEM>>>(
        pbh, pbl, pwqh, pwql, pqkvb, nullptr, nullptr,
        1024, 1024, 2048, 1024, nullptr, nullptr, 0);

    // remaining one-time weight conversions
    wconv<<<dim3(1024/32, 4096/32), 256>>>(w2, pw2h, pw2l, 4096, 1024);
    for (int l = 1; l < DEPTH; l++) {
        wconv<<<dim3(3072/32, 1024/32), 256>>>(wqkv + (long)l*1024*3072, pwqh + (long)l*3072*1024, pwql + (long)l*3072*1024, 1024, 3072);
        wconv<<<dim3(1024/32, 1024/32), 256>>>(wout + (long)l*1024*1024, pwoh + (long)l*1024*1024, pwol + (long)l*1024*1024, 1024, 1024);
        wconv<<<dim3(4096/32, 1024/32), 256>>>(w1   + (long)l*1024*4096, pw1h + (long)l*4096*1024, pw1l + (long)l*4096*1024, 1024, 4096);
        wconv<<<dim3(1024/32, 4096/32), 256>>>(w2   + (long)l*4096*1024, pw2h + (long)l*1024*4096, pw2l + (long)l*1024*4096, 4096, 1024);
    }

    for (int l = 0; l < DEPTH; l++) {
        bf16 *wqh = pwqh + (long)l*3072*1024, *wql = pwql + (long)l*3072*1024;
        bf16 *woh = pwoh + (long)l*1024*1024, *wol = pwol + (long)l*1024*1024;
        bf16 *w1h = pw1h + (long)l*4096*1024, *w1l = pw1l + (long)l*4096*1024;
        bf16 *w2h = pw2h + (long)l*1024*4096, *w2l = pw2l + (long)l*1024*4096;

        if (l > 0) {
            ln_k<true><<<MTOK, 256>>>(px, ln1g + l*DIMM, ln1b + l*DIMM, nullptr, phh, phl);
            bgemm<0><<<dim3(24, 32), 256, BG_SMEM>>>(
                phh, phl, wqh, wql, pqkv, nullptr, nullptr,
                1024, 1024, 3072, 1024, nullptr, nullptr, 0);
            bgemm<0><<<dim3(16, 32), 256, BG_SMEM>>>(
                pbh, pbl, wqh, wql, pqkvb, nullptr, nullptr,
                1024, 1024, 2048, 1024, nullptr, nullptr, 0);
        }

        pack_qk<<<(NBH*TT*128)/256, 256>>>(pqkv, pqkvb, pqh, pql, pkh, pkl, scale);
        vconv<<<dim3(32, 2, NBH), 256>>>(pqkv, pvh, pvl);

        flash_k<<<dim3(8, NBH), 256, FA_SMEM>>>(
            pqh, pql, pkh, pkl, pvh, pvl, paoh, paol);

        // x = x + ao @ Wout + bout
        bgemm<1><<<dim3(8, 32), 256, BG_SMEM>>>(
            paoh, paol, woh, wol, px, nullptr, nullptr,
            1024, 1024, 1024, 1024, bout + l*DIMM, px, 1024);

        // LN2 -> bf16 h
        ln_k<true><<<MTOK, 256>>>(px, ln2g + l*DIMM, ln2b + l*DIMM, nullptr, phh, phl);

        // ff = gelu(h @ W1 + b1) -> bf16
        bgemm<2><<<dim3(32, 32), 256, BG_SMEM>>>(
            phh, phl, w1h, w1l, nullptr, pfh, pfl,
            1024, 1024, 4096, 1024, b1 + l*FFI, nullptr, 0);

        // x = x + ff @ W2 + b2
        bgemm<1><<<dim3(8, 32), 256, BG_SMEM>>>(
            pfh, pfl, w2h, w2l, px, nullptr, nullptr,
            4096, 4096, 1024, 4096, b2 + l*DIMM, px, 1024);
    }

    ln_k<false><<<MTOK, 256>>>(px, lnfg, lnfb, (float*)d_out, nullptr, nullptr);
}

// round 9
// speedup vs baseline: 2.7063x; 1.0443x over previous
#include <cuda_runtime.h>
#include <cuda_bf16.h>
#include <math.h>

// ---------------------------------------------------------------------------
// TemporalTransformer forward. Dense GEMMs: bf16x3 split on mma.sync tensor
// cores (BK=32, 3-stage cp.async, 2 CTAs/SM). QKV projection fused with
// per-head pack/scale/transpose epilogue (no fp32 intermediates). Attention:
// fused flash kernel with double-buffered 64-row KV stages.
// NOTE: harness compiles for sm_100 (no 'a') -> tcgen05 unavailable.
// ---------------------------------------------------------------------------

#define DIMM   1024
#define DEPTH  4
#define HEADS  16
#define INNER  1024
#define FFI    4096
#define BB     4
#define TT     1024
#define MTOK   (BB*TT)
#define NBH    (BB*HEADS)

typedef __nv_bfloat16 bf16;
typedef __nv_bfloat162 bf162;

// -------------------- device-global scratch --------------------------------
__device__ float g_x   [MTOK*DIMM];

__device__ bf16 g_h_hi [MTOK*DIMM],      g_h_lo [MTOK*DIMM];
__device__ bf16 g_bias_hi[MTOK*DIMM],    g_bias_lo[MTOK*DIMM];
__device__ bf16 g_QQ_hi[NBH*TT*128],     g_QQ_lo[NBH*TT*128];
__device__ bf16 g_KK_hi[NBH*TT*128],     g_KK_lo[NBH*TT*128];
__device__ bf16 g_VT_hi[NBH*64*TT],      g_VT_lo[NBH*64*TT];
__device__ bf16 g_ao_hi[MTOK*INNER],     g_ao_lo[MTOK*INNER];
__device__ bf16 g_ff_hi[(long)MTOK*FFI], g_ff_lo[(long)MTOK*FFI];
__device__ bf16 g_wqkvT_hi[DEPTH*3072*1024], g_wqkvT_lo[DEPTH*3072*1024];
__device__ bf16 g_woutT_hi[DEPTH*1024*1024], g_woutT_lo[DEPTH*1024*1024];
__device__ bf16 g_w1T_hi [DEPTH*4096*1024], g_w1T_lo [DEPTH*4096*1024];
__device__ bf16 g_w2T_hi [DEPTH*1024*4096], g_w2T_lo [DEPTH*1024*4096];

// -------------------- helpers ----------------------------------------------
__device__ __forceinline__ bf162 mk2(bf16 a, bf16 b) {
    bf162 t; t.x = a; t.y = b; return t;
}

__device__ __forceinline__ void bsplit(float v, bf16& h, bf16& l) {
    bf16 hb = __float2bfloat16_rz(v);
    h = hb;
    l = __float2bfloat16(v - __bfloat162float(hb));
}

__device__ __forceinline__ unsigned pk2(bf16 a, bf16 b) {
    bf162 t; t.x = a; t.y = b;
    return *(unsigned*)&t;
}

__device__ __forceinline__ float gelu_f(float x) {
    return 0.5f * x * (1.0f + erff(x * 0.70710678118654752440f));
}

__device__ __forceinline__ void ldm4(unsigned& r0, unsigned& r1, unsigned& r2,
                                     unsigned& r3, unsigned a) {
    asm volatile("ldmatrix.sync.aligned.m8n8.x4.shared.b16 {%0,%1,%2,%3}, [%4];"
                 : "=r"(r0), "=r"(r1), "=r"(r2), "=r"(r3) : "r"(a));
}

__device__ __forceinline__ void mma16816(float* d, const unsigned* a,
                                         unsigned b0, unsigned b1) {
    asm volatile(
        "mma.sync.aligned.m16n8k16.row.col.f32.bf16.bf16.f32 "
        "{%0,%1,%2,%3}, {%4,%5,%6,%7}, {%8,%9}, {%0,%1,%2,%3};"
        : "+f"(d[0]), "+f"(d[1]), "+f"(d[2]), "+f"(d[3])
        : "r"(a[0]), "r"(a[1]), "r"(a[2]), "r"(a[3]), "r"(b0), "r"(b1));
}

__device__ __forceinline__ void cpa16(unsigned dst, const void* src) {
    asm volatile("cp.async.cg.shared.global [%0], [%1], 16;" :: "r"(dst), "l"(src));
}
__device__ __forceinline__ void cpcommit() { asm volatile("cp.async.commit_group;"); }
template<int N> __device__ __forceinline__ void cpwait() {
    asm volatile("cp.async.wait_group %0;" :: "n"(N));
}

// -------------------- block reductions (256 threads) -----------------------
__device__ __forceinline__ float blk_sum(float v) {
    __shared__ float sh[32];
    int lane = threadIdx.x & 31, w = threadIdx.x >> 5;
    #pragma unroll
    for (int o = 16; o; o >>= 1) v += __shfl_xor_sync(0xffffffffu, v, o);
    if (lane == 0) sh[w] = v;
    __syncthreads();
    if (w == 0) {
        v = (lane < 8) ? sh[lane] : 0.0f;
        #pragma unroll
        for (int o = 4; o; o >>= 1) v += __shfl_xor_sync(0xffffffffu, v, o);
        if (lane == 0) sh[0] = v;
    }
    __syncthreads();
    v = sh[0];
    __syncthreads();
    return v;
}

// -------------------- LayerNorm --------------------------------------------
template<bool BFOUT>
__global__ void ln_k(const float* __restrict__ x, const float* __restrict__ g,
                     const float* __restrict__ b, float* __restrict__ of,
                     bf16* __restrict__ ohi, bf16* __restrict__ olo) {
    long row = blockIdx.x;
    float4 v = ((const float4*)(x + row * DIMM))[threadIdx.x];
    float mu = blk_sum(v.x + v.y + v.z + v.w) * (1.0f / DIMM);
    float dx = v.x - mu, dy = v.y - mu, dz = v.z - mu, dw = v.w - mu;
    float var = blk_sum(dx*dx + dy*dy + dz*dz + dw*dw) * (1.0f / DIMM);
    float inv = rsqrtf(var + 1e-5f);
    float4 gg = ((const float4*)g)[threadIdx.x];
    float4 bb = ((const float4*)b)[threadIdx.x];
    float r0 = dx*inv*gg.x + bb.x, r1 = dy*inv*gg.y + bb.y;
    float r2 = dz*inv*gg.z + bb.z, r3 = dw*inv*gg.w + bb.w;
    if (BFOUT) {
        bf16 h0,l0,h1,l1,h2,l2,h3,l3;
        bsplit(r0,h0,l0); bsplit(r1,h1,l1); bsplit(r2,h2,l2); bsplit(r3,h3,l3);
        ((bf162*)(ohi + row*DIMM))[threadIdx.x*2]   = mk2(h0,h1);
        ((bf162*)(ohi + row*DIMM))[threadIdx.x*2+1] = mk2(h2,h3);
        ((bf162*)(olo + row*DIMM))[threadIdx.x*2]   = mk2(l0,l1);
        ((bf162*)(olo + row*DIMM))[threadIdx.x*2+1] = mk2(l2,l3);
    } else {
        float4 r; r.x=r0; r.y=r1; r.z=r2; r.w=r3;
        ((float4*)(of + row*DIMM))[threadIdx.x] = r;
    }
}

// -------------------- weight transpose+split: W[K][N] -> [N][K] hi/lo ------
__global__ void wconv(const float* __restrict__ W, bf16* __restrict__ hi,
                      bf16* __restrict__ lo, int K, int N) {
    __shared__ float t[32][33];
    int k0 = blockIdx.y * 32, n0 = blockIdx.x * 32;
    int tx = threadIdx.x & 31, ty = threadIdx.x >> 5;
    #pragma unroll
    for (int r = 0; r < 4; r++)
        t[ty + r*8][tx] = W[(long)(k0 + ty + r*8) * N + n0 + tx];
    __syncthreads();
    #pragma unroll
    for (int r = 0; r < 4; r++) {
        float v = t[tx][ty + r*8];
        long o = (long)(n0 + ty + r*8) * K + k0 + tx;
        bf16 h, l; bsplit(v, h, l);
        hi[o] = h; lo[o] = l;
    }
}

// -------------------- elementwise fp32 -> bf16 hi/lo -----------------------
__global__ void fconv(const float* __restrict__ s, bf16* __restrict__ hi,
                      bf16* __restrict__ lo) {
    long i = (long)blockIdx.x * blockDim.x + threadIdx.x;
    float4 v = ((const float4*)s)[i];
    bf16 h0,l0,h1,l1,h2,l2,h3,l3;
    bsplit(v.x,h0,l0); bsplit(v.y,h1,l1); bsplit(v.z,h2,l2); bsplit(v.w,h3,l3);
    ((bf162*)hi)[i*2]   = mk2(h0,h1);
    ((bf162*)hi)[i*2+1] = mk2(h2,h3);
    ((bf162*)lo)[i*2]   = mk2(l0,l1);
    ((bf162*)lo)[i*2+1] = mk2(l2,l3);
}

// -------------------- bf16x3 GEMM, BK=32, 3-stage, 2 CTAs/SM ----------------
// C[m,n] = sum_k A[m,k]*B[n,k]; A/B as (hi,lo) bf16 pairs, [row][k].
// EPI: 1 fp32 + bias[n] + resid; 2 gelu(+bias)->bf16 pair;
//      3 fused QKV pack epilogue (M=8192: rows<4096 = h @ W, rows>=4096 =
//        biasproj @ W; q/k scaled+packed per head into QQ/KK d-cols, V
//        transposed into VT; bias x V blocks early-exit).
#define BG_SMEM (3*32768)

__device__ __forceinline__ unsigned bg_off(int r, int c) {
    return (unsigned)(((r >> 1) << 7) + (((((r & 1) << 2) + c) ^ ((r >> 1) & 7)) << 4));
}

template<int EPI>
__global__ void __launch_bounds__(256, 2) bgemm(
    const bf16* __restrict__ Ahi, const bf16* __restrict__ Alo,
    const bf16* __restrict__ A2hi, const bf16* __restrict__ A2lo,
    const bf16* __restrict__ Bhi, const bf16* __restrict__ Blo,
    float* __restrict__ C, bf16* __restrict__ Chi, bf16* __restrict__ Clo,
    bf16* __restrict__ kkh, bf16* __restrict__ kkl,
    bf16* __restrict__ vth, bf16* __restrict__ vtl,
    int lda, int ldb, int ldc, int K,
    const float* __restrict__ bias, const float* __restrict__ resid, int ldr)
{
    const int bm0 = blockIdx.y * 128, bn0 = blockIdx.x * 128;
    const bool isBiasBlk = (EPI == 3) && (bm0 >= MTOK);
    if (EPI == 3 && isBiasBlk && bn0 >= 2048) return;   // bias rows have no V

    extern __shared__ __align__(128) char dsm[];
    const unsigned sb = (unsigned)__cvta_generic_to_shared(dsm);

    const bf16* Ah = isBiasBlk ? A2hi : Ahi;
    const bf16* Al = isBiasBlk ? A2lo : Alo;
    const int am0 = isBiasBlk ? (bm0 - MTOK) : bm0;

    const int tid = threadIdx.x, lane = tid & 31, wid = tid >> 5;
    const int wm = (wid >> 2) * 64, wn = (wid & 3) * 32;
    const int lr = lane & 15, h8 = lane >> 4;

    float acc[4][4][4];
    #pragma unroll
    for (int a = 0; a < 4; a++)
        #pragma unroll
        for (int b = 0; b < 4; b++)
            #pragma unroll
            for (int c = 0; c < 4; c++) acc[a][b][c] = 0.0f;

    auto loadStage = [&](int ch, int s) {
        unsigned base = sb + s * 32768;
        int k0 = ch << 5;
        #pragma unroll
        for (int i = 0; i < 2; i++) {
            int t = i * 256 + tid;
            int r = t >> 2, c = t & 3;
            unsigned so = bg_off(r, c);
            long goA = (long)(am0 + r) * lda + k0 + c * 8;
            long goB = (long)(bn0 + r) * ldb + k0 + c * 8;
            cpa16(base + so,         Ah + goA);
            cpa16(base + 8192 + so,  Al + goA);
            cpa16(base + 16384 + so, Bhi + goB);
            cpa16(base + 24576 + so, Blo + goB);
        }
    };

    auto comp = [&](int s) {
        unsigned aH = sb + s * 32768;
        unsigned aL = aH + 8192, bH = aH + 16384, bL = aH + 24576;
        #pragma unroll
        for (int ks = 0; ks < 2; ks++) {
            int cc = ks * 2 + h8;
            unsigned AH[4][4], AL[4][4];
            #pragma unroll
            for (int mf = 0; mf < 4; mf++) {
                unsigned off = bg_off(wm + mf * 16 + lr, cc);
                ldm4(AH[mf][0], AH[mf][1], AH[mf][2], AH[mf][3], aH + off);
                ldm4(AL[mf][0], AL[mf][1], AL[mf][2], AL[mf][3], aL + off);
            }
            #pragma unroll
            for (int p = 0; p < 2; p++) {
                unsigned off = bg_off(wn + p * 16 + lr, cc);
                unsigned BH[4], BL[4];
                ldm4(BH[0], BH[1], BH[2], BH[3], bH + off);
                ldm4(BL[0], BL[1], BL[2], BL[3], bL + off);
                #pragma unroll
                for (int mf = 0; mf < 4; mf++) {
                    mma16816(acc[mf][2*p],   AH[mf], BH[0], BH[2]);
                    mma16816(acc[mf][2*p],   AH[mf], BL[0], BL[2]);
                    mma16816(acc[mf][2*p],   AL[mf], BH[0], BH[2]);
                    mma16816(acc[mf][2*p+1], AH[mf], BH[1], BH[3]);
                    mma16816(acc[mf][2*p+1], AH[mf], BL[1], BL[3]);
                    mma16816(acc[mf][2*p+1], AL[mf], BH[1], BH[3]);
                }
            }
        }
    };

    const int nch = K >> 5;
    loadStage(0, 0); cpcommit();
    loadStage(1, 1); cpcommit();
    int slot = 0;
    for (int ch = 0; ch < nch; ch++) {
        if (ch + 1 < nch) { cpwait<1>(); } else { cpwait<0>(); }
        __syncthreads();
        if (ch + 2 < nch) {
            int ns = slot + 2; if (ns >= 3) ns -= 3;
            loadStage(ch + 2, ns); cpcommit();
        }
        comp(slot);
        if (++slot == 3) slot = 0;
    }

    // epilogue
    #pragma unroll
    for (int mf = 0; mf < 4; mf++)
        #pragma unroll
        for (int nf = 0; nf < 4; nf++)
            #pragma unroll
            for (int r = 0; r < 2; r++) {
                int m = bm0 + wm + mf * 16 + (lane >> 2) + r * 8;
                int n = bn0 + wn + nf * 8 + (lane & 3) * 2;
                float v0 = acc[mf][nf][r*2], v1 = acc[mf][nf][r*2+1];
                if constexpr (EPI == 1) {
                    long o = (long)m * ldc + n;
                    float2 w;
                    w.x = v0 + bias[n] + resid[(long)m * ldr + n];
                    w.y = v1 + bias[n+1] + resid[(long)m * ldr + n + 1];
                    *(float2*)&C[o] = w;
                } else if constexpr (EPI == 2) {
                    long o = (long)m * ldc + n;
                    v0 = gelu_f(v0 + bias[n]);
                    v1 = gelu_f(v1 + bias[n+1]);
                    bf16 h0,l0,h1,l1;
                    bsplit(v0,h0,l0); bsplit(v1,h1,l1);
                    *(bf162*)&Chi[o] = mk2(h0,h1);
                    *(bf162*)&Clo[o] = mk2(l0,l1);
                } else {  // EPI == 3: QKV pack
                    int isB = (m >= MTOK);
                    int tok = m & (MTOK-1);
                    int bb2 = tok >> 10, ii = tok & 1023;
                    if (n < 2048) {
                        int n2 = n & 1023;
                        int hh = n2 >> 6;
                        int d  = (n2 & 63) + (isB ? 64 : 0);
                        long o = ((long)((bb2 << 4) + hh) * 1024 + ii) * 128 + d;
                        bf16* oh; bf16* ol;
                        if (n < 1024) { v0 *= 0.125f; v1 *= 0.125f; oh = Chi; ol = Clo; }
                        else          { oh = kkh; ol = kkl; }
                        bf16 h0,l0,h1,l1;
                        bsplit(v0,h0,l0); bsplit(v1,h1,l1);
                        *(bf162*)&oh[o] = mk2(h0,h1);
                        *(bf162*)&ol[o] = mk2(l0,l1);
                    } else if (!isB) {
                        int n2 = n - 2048;
                        int hh = n2 >> 6, d = n2 & 63;
                        long o = ((long)((bb2 << 4) + hh) * 64 + d) * 1024 + ii;
                        bf16 h0,l0,h1,l1;
                        bsplit(v0,h0,l0); bsplit(v1,h1,l1);
                        vth[o] = h0;        vtl[o] = l0;
                        vth[o + 1024] = h1; vtl[o + 1024] = l1;
                    }
                }
            }
}

// -------------------- fused flash attention (double-buffered KV) -----------
// Q tile 128x128 resident; 16 KV tiles of 64 rows, 2-stage cp.async pipeline.
// Stage (48KB): KH 16K | KL 16K | VH 8K | VL 8K. Total smem 160KB.
#define FB_SQH 0
#define FB_SQL 32768
#define FB_STG 65536
#define FB_STGSZ 49152
#define FB_SMEM (65536 + 2*FB_STGSZ)

__global__ void __launch_bounds__(256) flash_k(
    const bf16* __restrict__ Qh, const bf16* __restrict__ Ql,
    const bf16* __restrict__ Kh, const bf16* __restrict__ Kl,
    const bf16* __restrict__ Vh, const bf16* __restrict__ Vl,
    bf16* __restrict__ Ohi, bf16* __restrict__ Olo)
{
    extern __shared__ __align__(128) char fsm[];
    const unsigned sb = (unsigned)__cvta_generic_to_shared(fsm);

    const int mt = blockIdx.x, bh = blockIdx.y;
    const int m0 = mt * 128;
    const int tid = threadIdx.x, lane = tid & 31, wid = tid >> 5;
    const int wm = wid * 16;
    const int lr = lane & 15, h8 = lane >> 4;

    const bf16* Qhp = Qh + ((long)bh * TT + m0) * 128;
    const bf16* Qlp = Ql + ((long)bh * TT + m0) * 128;
    const bf16* Khp = Kh + (long)bh * TT * 128;
    const bf16* Klp = Kl + (long)bh * TT * 128;
    const bf16* Vhp = Vh + (long)bh * 64 * TT;
    const bf16* Vlp = Vl + (long)bh * 64 * TT;

    // Q tile: 128 rows x 16 chunks, hi+lo (group 0)
    #pragma unroll 4
    for (int t = tid; t < 2048; t += 256) {
        int r = t >> 4, c = t & 15;
        long go = (long)r * 128 + c * 8;
        unsigned so = (unsigned)(((r << 4) + (c ^ (r & 7))) << 4);
        cpa16(sb + FB_SQH + so, Qhp + go);
        cpa16(sb + FB_SQL + so, Qlp + go);
    }
    cpcommit();

    auto loadKV = [&](int jt, int s) {
        unsigned base = sb + FB_STG + s * FB_STGSZ;
        #pragma unroll 2
        for (int t = tid; t < 1024; t += 256) {     // K: 64 rows x 16 chunks
            int r = t >> 4, c = t & 15;
            long go = (long)(jt * 64 + r) * 128 + c * 8;
            unsigned so = (unsigned)(((r << 4) + (c ^ (r & 7))) << 4);
            cpa16(base + so, Khp + go);
            cpa16(base + 16384 + so, Klp + go);
        }
        #pragma unroll 2
        for (int t = tid; t < 512; t += 256) {      // V^T: 64 d-rows x 8 chunks
            int r = t >> 3, c = t & 7;
            long go = (long)r * TT + jt * 64 + c * 8;
            unsigned so = (unsigned)(((r << 3) + (c ^ (r & 7))) << 4);
            cpa16(base + 32768 + so, Vhp + go);
            cpa16(base + 40960 + so, Vlp + go);
        }
    };

    loadKV(0, 0); cpcommit();
    loadKV(1, 1); cpcommit();

    float oacc[8][4];
    #pragma unroll
    for (int i = 0; i < 8; i++)
        #pragma unroll
        for (int j = 0; j < 4; j++) oacc[i][j] = 0.0f;
    float mrow0 = -INFINITY, mrow1 = -INFINITY;
    float lrow0 = 0.0f, lrow1 = 0.0f;

    for (int jt = 0; jt < 16; jt++) {
        int s = jt & 1;
        unsigned stg = sb + FB_STG + s * FB_STGSZ;
        if (jt + 2 <= 15) { cpwait<1>(); } else { cpwait<0>(); }
        __syncthreads();

        // ---- S = Q' K'^T over feature dim 128 (8 ksteps), 64 kv cols ----
        float sacc[8][4];
        #pragma unroll
        for (int i = 0; i < 8; i++)
            #pragma unroll
            for (int j = 0; j < 4; j++) sacc[i][j] = 0.0f;

        #pragma unroll
        for (int ks = 0; ks < 8; ks++) {
            int c = ks * 2 + h8;
            unsigned AH[4], AL[4];
            {
                int row = wm + lr;
                unsigned off = (unsigned)(((row << 4) + (c ^ (row & 7))) << 4);
                ldm4(AH[0], AH[1], AH[2], AH[3], sb + FB_SQH + off);
                ldm4(AL[0], AL[1], AL[2], AL[3], sb + FB_SQL + off);
            }
            #pragma unroll
            for (int p = 0; p < 4; p++) {
                int row = p * 16 + lr;
                unsigned off = (unsigned)(((row << 4) + (c ^ (row & 7))) << 4);
                unsigned BH[4], BL[4];
                ldm4(BH[0], BH[1], BH[2], BH[3], stg + off);
                ldm4(BL[0], BL[1], BL[2], BL[3], stg + 16384 + off);
                mma16816(sacc[2*p],   AH, BH[0], BH[2]);
                mma16816(sacc[2*p],   AH, BL[0], BL[2]);
                mma16816(sacc[2*p],   AL, BH[0], BH[2]);
                mma16816(sacc[2*p+1], AH, BH[1], BH[3]);
                mma16816(sacc[2*p+1], AH, BL[1], BL[3]);
                mma16816(sacc[2*p+1], AL, BH[1], BH[3]);
            }
        }

        // ---- online softmax update (64 cols) ----
        float tm0 = -INFINITY, tm1 = -INFINITY;
        #pragma unroll
        for (int nf = 0; nf < 8; nf++) {
            tm0 = fmaxf(tm0, fmaxf(sacc[nf][0], sacc[nf][1]));
            tm1 = fmaxf(tm1, fmaxf(sacc[nf][2], sacc[nf][3]));
        }
        tm0 = fmaxf(tm0, __shfl_xor_sync(0xffffffffu, tm0, 1));
        tm0 = fmaxf(tm0, __shfl_xor_sync(0xffffffffu, tm0, 2));
        tm1 = fmaxf(tm1, __shfl_xor_sync(0xffffffffu, tm1, 1));
        tm1 = fmaxf(tm1, __shfl_xor_sync(0xffffffffu, tm1, 2));
        float mn0 = fmaxf(mrow0, tm0), mn1 = fmaxf(mrow1, tm1);
        float cor0 = __expf(mrow0 - mn0), cor1 = __expf(mrow1 - mn1);
        mrow0 = mn0; mrow1 = mn1;
        #pragma unroll
        for (int nf = 0; nf < 8; nf++) {
            oacc[nf][0] *= cor0; oacc[nf][1] *= cor0;
            oacc[nf][2] *= cor1; oacc[nf][3] *= cor1;
        }

        // ---- P = exp(S - m), split, O += P V (4 ksteps of 16 t) ----
        float rs0 = 0.0f, rs1 = 0.0f;
        #pragma unroll
        for (int ks = 0; ks < 4; ks++) {
            float p00 = __expf(sacc[2*ks][0]   - mn0);
            float p01 = __expf(sacc[2*ks][1]   - mn0);
            float p02 = __expf(sacc[2*ks][2]   - mn1);
            float p03 = __expf(sacc[2*ks][3]   - mn1);
            float p10 = __expf(sacc[2*ks+1][0] - mn0);
            float p11 = __expf(sacc[2*ks+1][1] - mn0);
            float p12 = __expf(sacc[2*ks+1][2] - mn1);
            float p13 = __expf(sacc[2*ks+1][3] - mn1);
            rs0 += p00 + p01 + p10 + p11;
            rs1 += p02 + p03 + p12 + p13;
            bf16 h, l, h2, l2;
            unsigned PH[4], PL[4];
            bsplit(p00, h, l); bsplit(p01, h2, l2);
            PH[0] = pk2(h, h2); PL[0] = pk2(l, l2);
            bsplit(p02, h, l); bsplit(p03, h2, l2);
            PH[1] = pk2(h, h2); PL[1] = pk2(l, l2);
            bsplit(p10, h, l); bsplit(p11, h2, l2);
            PH[2] = pk2(h, h2); PL[2] = pk2(l, l2);
            bsplit(p12, h, l); bsplit(p13, h2, l2);
            PH[3] = pk2(h, h2); PL[3] = pk2(l, l2);

            int c = ks * 2 + h8;
            #pragma unroll
            for (int p = 0; p < 4; p++) {
                int row = p * 16 + lr;
                unsigned off = (unsigned)(((row << 3) + (c ^ (row & 7))) << 4);
                unsigned BH[4], BL[4];
                ldm4(BH[0], BH[1], BH[2], BH[3], stg + 32768 + off);
                ldm4(BL[0], BL[1], BL[2], BL[3], stg + 40960 + off);
                mma16816(oacc[2*p],   PH, BH[0], BH[2]);
                mma16816(oacc[2*p],   PH, BL[0], BL[2]);
                mma16816(oacc[2*p],   PL, BH[0], BH[2]);
                mma16816(oacc[2*p+1], PH, BH[1], BH[3]);
                mma16816(oacc[2*p+1], PH, BL[1], BL[3]);
                mma16816(oacc[2*p+1], PL, BH[1], BH[3]);
            }
        }
        rs0 += __shfl_xor_sync(0xffffffffu, rs0, 1);
        rs0 += __shfl_xor_sync(0xffffffffu, rs0, 2);
        rs1 += __shfl_xor_sync(0xffffffffu, rs1, 1);
        rs1 += __shfl_xor_sync(0xffffffffu, rs1, 2);
        lrow0 = lrow0 * cor0 + rs0;
        lrow1 = lrow1 * cor1 + rs1;

        __syncthreads();
        if (jt + 2 < 16) { loadKV(jt + 2, s); cpcommit(); }
    }

    // ---- epilogue ----
    float inv0 = 1.0f / lrow0, inv1 = 1.0f / lrow1;
    int b = bh >> 4, h = bh & 15;
    int r0 = m0 + wm + (lane >> 2);
    int cb = h * 64 + (lane & 3) * 2;
    bf16* oh0 = Ohi + ((long)(b * TT + r0)) * INNER + cb;
    bf16* ol0 = Olo + ((long)(b * TT + r0)) * INNER + cb;
    bf16* oh1 = oh0 + 8L * INNER;
    bf16* ol1 = ol0 + 8L * INNER;
    #pragma unroll
    for (int nf = 0; nf < 8; nf++) {
        bf16 ha, la, hb2, lb2;
        bsplit(oacc[nf][0] * inv0, ha, la);
        bsplit(oacc[nf][1] * inv0, hb2, lb2);
        *(bf162*)(oh0 + nf * 8) = mk2(ha, hb2);
        *(bf162*)(ol0 + nf * 8) = mk2(la, lb2);
        bsplit(oacc[nf][2] * inv1, ha, la);
        bsplit(oacc[nf][3] * inv1, hb2, lb2);
        *(bf162*)(oh1 + nf * 8) = mk2(ha, hb2);
        *(bf162*)(ol1 + nf * 8) = mk2(la, lb2);
    }
}

// -------------------- host orchestration -----------------------------------
extern "C" void kernel_launch(void* const* d_in, const int* in_sizes, int n_in,
                              void* d_out, int out_size) {
    (void)in_sizes; (void)n_in; (void)out_size;
    const float* x    = (const float*)d_in[0];
    const float* bias = (const float*)d_in[1];
    const float* wqkv = (const float*)d_in[2];
    const float* wout = (const float*)d_in[3];
    const float* bout = (const float*)d_in[4];
    const float* ln1g = (const float*)d_in[5];
    const float* ln1b = (const float*)d_in[6];
    const float* w1   = (const float*)d_in[7];
    const float* b1   = (const float*)d_in[8];
    const float* w2   = (const float*)d_in[9];
    const float* b2   = (const float*)d_in[10];
    const float* ln2g = (const float*)d_in[11];
    const float* ln2b = (const float*)d_in[12];
    const float* lnfg = (const float*)d_in[13];
    const float* lnfb = (const float*)d_in[14];

    float *px;
    bf16 *phh, *phl, *pbh, *pbl, *pqh, *pql, *pkh, *pkl, *pvh, *pvl;
    bf16 *paoh, *paol, *pfh, *pfl;
    bf16 *pwqh, *pwql, *pwoh, *pwol, *pw1h, *pw1l, *pw2h, *pw2l;
    cudaGetSymbolAddress((void**)&px,    g_x);
    cudaGetSymbolAddress((void**)&phh,   g_h_hi);    cudaGetSymbolAddress((void**)&phl, g_h_lo);
    cudaGetSymbolAddress((void**)&pbh,   g_bias_hi); cudaGetSymbolAddress((void**)&pbl, g_bias_lo);
    cudaGetSymbolAddress((void**)&pqh,   g_QQ_hi);   cudaGetSymbolAddress((void**)&pql, g_QQ_lo);
    cudaGetSymbolAddress((void**)&pkh,   g_KK_hi);   cudaGetSymbolAddress((void**)&pkl, g_KK_lo);
    cudaGetSymbolAddress((void**)&pvh,   g_VT_hi);   cudaGetSymbolAddress((void**)&pvl, g_VT_lo);
    cudaGetSymbolAddress((void**)&paoh,  g_ao_hi);   cudaGetSymbolAddress((void**)&paol, g_ao_lo);
    cudaGetSymbolAddress((void**)&pfh,   g_ff_hi);   cudaGetSymbolAddress((void**)&pfl, g_ff_lo);
    cudaGetSymbolAddress((void**)&pwqh,  g_wqkvT_hi); cudaGetSymbolAddress((void**)&pwql, g_wqkvT_lo);
    cudaGetSymbolAddress((void**)&pwoh,  g_woutT_hi); cudaGetSymbolAddress((void**)&pwol, g_woutT_lo);
    cudaGetSymbolAddress((void**)&pw1h,  g_w1T_hi);  cudaGetSymbolAddress((void**)&pw1l, g_w1T_lo);
    cudaGetSymbolAddress((void**)&pw2h,  g_w2T_hi);  cudaGetSymbolAddress((void**)&pw2l, g_w2T_lo);

    cudaFuncSetAttribute(bgemm<1>, cudaFuncAttributeMaxDynamicSharedMemorySize, BG_SMEM);
    cudaFuncSetAttribute(bgemm<2>, cudaFuncAttributeMaxDynamicSharedMemorySize, BG_SMEM);
    cudaFuncSetAttribute(bgemm<3>, cudaFuncAttributeMaxDynamicSharedMemorySize, BG_SMEM);
    cudaFuncSetAttribute(flash_k, cudaFuncAttributeMaxDynamicSharedMemorySize, FB_SMEM);

    cudaMemcpyAsync(px, x, sizeof(float) * MTOK * DIMM, cudaMemcpyDeviceToDevice);

    // one-time conversions
    fconv<<<MTOK*DIMM/1024, 256>>>(bias, pbh, pbl);
    for (int l = 0; l < DEPTH; l++) {
        wconv<<<dim3(3072/32, 1024/32), 256>>>(wqkv + (long)l*1024*3072, pwqh + (long)l*3072*1024, pwql + (long)l*3072*1024, 1024, 3072);
        wconv<<<dim3(1024/32, 1024/32), 256>>>(wout + (long)l*1024*1024, pwoh + (long)l*1024*1024, pwol + (long)l*1024*1024, 1024, 1024);
        wconv<<<dim3(4096/32, 1024/32), 256>>>(w1   + (long)l*1024*4096, pw1h + (long)l*4096*1024, pw1l + (long)l*4096*1024, 1024, 4096);
        wconv<<<dim3(1024/32, 4096/32), 256>>>(w2   + (long)l*4096*1024, pw2h + (long)l*1024*4096, pw2l + (long)l*1024*4096, 4096, 1024);
    }

    for (int l = 0; l < DEPTH; l++) {
        bf16 *wqh = pwqh + (long)l*3072*1024, *wql = pwql + (long)l*3072*1024;
        bf16 *woh = pwoh + (long)l*1024*1024, *wol = pwol + (long)l*1024*1024;
        bf16 *w1h = pw1h + (long)l*4096*1024, *w1l = pw1l + (long)l*4096*1024;
        bf16 *w2h = pw2h + (long)l*1024*4096, *w2l = pw2l + (long)l*1024*4096;

        // LN1 -> bf16 h
        ln_k<true><<<MTOK, 256>>>(px, ln1g + l*DIMM, ln1b + l*DIMM, nullptr, phh, phl);

        // merged QKV projection (h rows + bias rows) with fused pack epilogue
        bgemm<3><<<dim3(24, 64), 256, BG_SMEM>>>(
            phh, phl, pbh, pbl, wqh, wql,
            nullptr, pqh, pql, pkh, pkl, pvh, pvl,
            1024, 1024, 0, 1024, nullptr, nullptr, 0);

        // fused flash attention -> ao (bf16 hi/lo, token-major)
        flash_k<<<dim3(8, NBH), 256, FB_SMEM>>>(
            pqh, pql, pkh, pkl, pvh, pvl, paoh, paol);

        // x = x + ao @ Wout + bout
        bgemm<1><<<dim3(8, 32), 256, BG_SMEM>>>(
            paoh, paol, nullptr, nullptr, woh, wol,
            px, nullptr, nullptr, nullptr, nullptr, nullptr, nullptr,
            1024, 1024, 1024, 1024, bout + l*DIMM, px, 1024);

        // LN2 -> bf16 h
        ln_k<true><<<MTOK, 256>>>(px, ln2g + l*DIMM, ln2b + l*DIMM, nullptr, phh, phl);

        // ff = gelu(h @ W1 + b1) -> bf16
        bgemm<2><<<dim3(32, 32), 256, BG_SMEM>>>(
            phh, phl, nullptr, nullptr, w1h, w1l,
            nullptr, pfh, pfl, nullptr, nullptr, nullptr, nullptr,
            1024, 1024, 4096, 1024, b1 + l*FFI, nullptr, 0);

        // x = x + ff @ W2 + b2
        bgemm<1><<<dim3(8, 32), 256, BG_SMEM>>>(
            pfh, pfl, nullptr, nullptr, w2h, w2l,
            px, nullptr, nullptr, nullptr, nullptr, nullptr, nullptr,
            4096, 4096, 1024, 4096, b2 + l*DIMM, px, 1024);
    }

    // final LN -> fp32 out
    ln_k<false><<<MTOK, 256>>>(px, lnfg, lnfb, (float*)d_out, nullptr, nullptr);
}